// round 7
// baseline (speedup 1.0000x reference)
#include <cuda_runtime.h>
#include <cuda_bf16.h>
#include <math.h>
#include <stdint.h>

#define N_TOK        8192
#define DMODEL       1024
#define DQUERY       256
#define NHEADS       4
#define NSUB         128
#define TOPK         8
#define DLATENT      256
#define DHIDDEN      512
#define NEXPERTS     16384
#define NEG_INF      (-1.0e38f)

// ---------------- scratch (device globals; no allocation allowed) ----------------
__device__ float g_q[N_TOK * DMODEL];
__device__ float g_qh[N_TOK * DMODEL];
__device__ float g_ql[N_TOK * DMODEL];
__device__ float g_s1[N_TOK * NHEADS * NSUB];
__device__ float g_s2[N_TOK * NHEADS * NSUB];
__device__ float g_scale[DMODEL];
__device__ float g_shift[DMODEL];
__device__ float g_bnpart[16 * DMODEL];
__device__ float g_Hall[NEXPERTS * DHIDDEN];
__device__ float g_xproj[N_TOK * DHIDDEN];
__device__ float g_probs[N_TOK * NHEADS * TOPK];
__device__ int   g_eidx[N_TOK * NHEADS * TOPK];
__device__ float g_W1T[DHIDDEN * DLATENT];
__device__ float g_WvT[DMODEL * DHIDDEN];
// tf32 split pairs (stored as fp32)
__device__ float g_xh[N_TOK * DMODEL];
__device__ float g_xl[N_TOK * DMODEL];
__device__ float g_wqh[DMODEL * DMODEL];
__device__ float g_wql[DMODEL * DMODEL];
__device__ float g_sk1h[NSUB * 128];
__device__ float g_sk1l[NSUB * 128];
__device__ float g_sk2h[NSUB * 128];
__device__ float g_sk2l[NSUB * 128];
// bf16 split pairs
__device__ __nv_bfloat16 g_xbh[N_TOK * DMODEL];
__device__ __nv_bfloat16 g_xbl[N_TOK * DMODEL];
__device__ __nv_bfloat16 g_lath[NEXPERTS * DLATENT];
__device__ __nv_bfloat16 g_latl[NEXPERTS * DLATENT];
__device__ __nv_bfloat16 g_w1th[DHIDDEN * DLATENT];
__device__ __nv_bfloat16 g_w1tl[DHIDDEN * DLATENT];
__device__ __nv_bfloat16 g_w2h[DHIDDEN * DMODEL];
__device__ __nv_bfloat16 g_w2l[DHIDDEN * DMODEL];
__device__ __nv_bfloat16 g_wvth[DMODEL * DHIDDEN];
__device__ __nv_bfloat16 g_wvtl[DMODEL * DHIDDEN];
__device__ __nv_bfloat16 g_acch[N_TOK * DHIDDEN];
__device__ __nv_bfloat16 g_accl[N_TOK * DHIDDEN];

__device__ __forceinline__ float gelu_exact(float x) {
    return 0.5f * x * (1.0f + erff(x * 0.70710678118654752f));
}
__device__ __forceinline__ uint32_t smem_u32(const void* p) {
    uint32_t a;
    asm("{ .reg .u64 t; cvta.to.shared.u64 t, %1; cvt.u32.u64 %0, t; }" : "=r"(a) : "l"(p));
    return a;
}
__device__ __forceinline__ uint32_t sw128(uint32_t o) { return o ^ ((o >> 3) & 0x70); }
__device__ __forceinline__ uint32_t f2tf(float x) {
    uint32_t u;
    asm("cvt.rna.tf32.f32 %0, %1;" : "=r"(u) : "f"(x));
    return u;
}

// ---------------- cp.async helpers (sm_80 baseline PTX) ----------------
__device__ __forceinline__ void cp16(uint32_t dst, const void* src) {
    asm volatile("cp.async.cg.shared.global [%0], [%1], 16;"
                 :: "r"(dst), "l"(__cvta_generic_to_global(src)));
}
__device__ __forceinline__ void cp_commit() {
    asm volatile("cp.async.commit_group;" ::: "memory");
}
__device__ __forceinline__ void cp_wait0() {
    asm volatile("cp.async.wait_group 0;" ::: "memory");
}

// ================================================================
// split kernels (one-time conversion)
// ================================================================
__global__ void __launch_bounds__(256)
split_tf32_kernel(const float* __restrict__ src, float* __restrict__ hi, float* __restrict__ lo)
{
    const int i = blockIdx.x * 256 + threadIdx.x;
    float4 v = reinterpret_cast<const float4*>(src)[i];
    float4 h = make_float4(__uint_as_float(f2tf(v.x)), __uint_as_float(f2tf(v.y)),
                           __uint_as_float(f2tf(v.z)), __uint_as_float(f2tf(v.w)));
    float4 l;
    l.x = __uint_as_float(f2tf(v.x - h.x));
    l.y = __uint_as_float(f2tf(v.y - h.y));
    l.z = __uint_as_float(f2tf(v.z - h.z));
    l.w = __uint_as_float(f2tf(v.w - h.w));
    reinterpret_cast<float4*>(hi)[i] = h;
    reinterpret_cast<float4*>(lo)[i] = l;
}

__device__ __forceinline__ void bf_split4(float4 v, uint2& hp, uint2& lp)
{
    __nv_bfloat16 h0 = __float2bfloat16(v.x);
    __nv_bfloat16 h1 = __float2bfloat16(v.y);
    __nv_bfloat16 h2 = __float2bfloat16(v.z);
    __nv_bfloat16 h3 = __float2bfloat16(v.w);
    __nv_bfloat16 l0 = __float2bfloat16(v.x - __bfloat162float(h0));
    __nv_bfloat16 l1 = __float2bfloat16(v.y - __bfloat162float(h1));
    __nv_bfloat16 l2 = __float2bfloat16(v.z - __bfloat162float(h2));
    __nv_bfloat16 l3 = __float2bfloat16(v.w - __bfloat162float(h3));
    hp.x = ((uint32_t)__bfloat16_as_ushort(h1) << 16) | __bfloat16_as_ushort(h0);
    hp.y = ((uint32_t)__bfloat16_as_ushort(h3) << 16) | __bfloat16_as_ushort(h2);
    lp.x = ((uint32_t)__bfloat16_as_ushort(l1) << 16) | __bfloat16_as_ushort(l0);
    lp.y = ((uint32_t)__bfloat16_as_ushort(l3) << 16) | __bfloat16_as_ushort(l2);
}

__global__ void __launch_bounds__(256)
split_bf16_kernel(const float* __restrict__ src,
                  __nv_bfloat16* __restrict__ hi, __nv_bfloat16* __restrict__ lo)
{
    const int i = blockIdx.x * 256 + threadIdx.x;
    float4 v = reinterpret_cast<const float4*>(src)[i];
    uint2 hp, lp;
    bf_split4(v, hp, lp);
    reinterpret_cast<uint2*>(hi)[i] = hp;
    reinterpret_cast<uint2*>(lo)[i] = lp;
}

// strided source (row stride sld, take cols4*4 cols per row), dense dest
__global__ void __launch_bounds__(256)
split_bf16_strided(const float* __restrict__ src, int sld, int cols4,
                   __nv_bfloat16* __restrict__ hi, __nv_bfloat16* __restrict__ lo)
{
    const int i = blockIdx.x * 256 + threadIdx.x;
    const int row = i / cols4, c4 = i % cols4;
    float4 v = *reinterpret_cast<const float4*>(src + (size_t)row * sld + c4 * 4);
    uint2 hp, lp;
    bf_split4(v, hp, lp);
    reinterpret_cast<uint2*>(hi)[i] = hp;
    reinterpret_cast<uint2*>(lo)[i] = lp;
}

// ================================================================
// 3xTF32 tensor-core GEMM — cp.async pipeline on pre-split operands
// ================================================================
__device__ __forceinline__ void mma_tf32(float* d, const uint32_t* a, uint32_t b0, uint32_t b1) {
    asm volatile(
        "mma.sync.aligned.m16n8k8.row.col.f32.tf32.tf32.f32 "
        "{%0,%1,%2,%3}, {%4,%5,%6,%7}, {%8,%9}, {%0,%1,%2,%3};"
        : "+f"(d[0]), "+f"(d[1]), "+f"(d[2]), "+f"(d[3])
        : "r"(a[0]), "r"(a[1]), "r"(a[2]), "r"(a[3]), "r"(b0), "r"(b1));
}

#define TF_ST 36
#define TF_TILE_FLOATS (128 * TF_ST)
#define TF_TILE_BYTES  (TF_TILE_FLOATS * 4)
#define TF_STAGE_FLOATS (4 * TF_TILE_FLOATS)
#define TF_STAGE_BYTES  (4 * TF_TILE_BYTES)
#define TF_GEMM_SMEM   (2 * TF_STAGE_BYTES + 1024)

// tile: 128 rows x 32 fp32, padded row stride 36 floats
__device__ __forceinline__ void tf_cp_tile(uint32_t sm, const float* __restrict__ src,
                                           int ld, int tid)
{
    const int row = tid >> 1;
    const int cb = (tid & 1) * 4;
    const float* s = src + (size_t)row * ld + cb * 4;
#pragma unroll
    for (int j = 0; j < 4; j++) {
        uint32_t off = (uint32_t)(row * TF_ST + (cb + j) * 4) * 4;
        cp16(sm + off, s + j * 4);
    }
}

__global__ void __launch_bounds__(256, 1)
tf32_gemm(const float* __restrict__ Ah0, const float* __restrict__ Al0, int lda,
          const float* __restrict__ Bh0, const float* __restrict__ Bl0, int ldb,
          float* __restrict__ C, int ldc, int K,
          const float* __restrict__ bias)
{
    extern __shared__ char dsm[];
    const uint32_t raw = smem_u32(dsm);
    const uint32_t base = (raw + 1023) & ~1023u;
    float* tiles = reinterpret_cast<float*>(dsm + (base - raw));

    const int tid  = threadIdx.x;
    const int lane = tid & 31;
    const int wid  = tid >> 5;
    const int wm = wid & 3;
    const int wn = wid >> 2;
    const int grp = lane >> 2;
    const int tig = lane & 3;
    const int bm = blockIdx.y * 128;
    const int bn = blockIdx.x * 128;

    const float* Ah = Ah0 + (size_t)bm * lda;
    const float* Al = Al0 + (size_t)bm * lda;
    const float* Bh = Bh0 + (size_t)bn * ldb;
    const float* Bl = Bl0 + (size_t)bn * ldb;
    const int nk = K >> 5;

    // prologue
    {
        const uint32_t sb = base;
        tf_cp_tile(sb,                    Ah, lda, tid);
        tf_cp_tile(sb +     TF_TILE_BYTES, Al, lda, tid);
        tf_cp_tile(sb + 2 * TF_TILE_BYTES, Bh, ldb, tid);
        tf_cp_tile(sb + 3 * TF_TILE_BYTES, Bl, ldb, tid);
        cp_commit();
        cp_wait0();
        __syncthreads();
    }

    float acc[2][8][4];
#pragma unroll
    for (int i = 0; i < 2; i++)
#pragma unroll
        for (int j = 0; j < 8; j++)
#pragma unroll
            for (int t = 0; t < 4; t++) acc[i][j][t] = 0.f;

    const int ar = wm * 32 + grp;
    const int br = wn * 64 + grp;

    for (int kc = 0; kc < nk; kc++) {
        const int cur = kc & 1;
        const bool more = (kc + 1 < nk);
        if (more) {
            const uint32_t sb = base + (cur ^ 1) * TF_STAGE_BYTES;
            tf_cp_tile(sb,                    Ah + (kc + 1) * 32, lda, tid);
            tf_cp_tile(sb +     TF_TILE_BYTES, Al + (kc + 1) * 32, lda, tid);
            tf_cp_tile(sb + 2 * TF_TILE_BYTES, Bh + (kc + 1) * 32, ldb, tid);
            tf_cp_tile(sb + 3 * TF_TILE_BYTES, Bl + (kc + 1) * 32, ldb, tid);
            cp_commit();
        }
        const float* sAh = tiles + cur * TF_STAGE_FLOATS;
        const float* sAl = sAh + TF_TILE_FLOATS;
        const float* sBh = sAl + TF_TILE_FLOATS;
        const float* sBl = sBh + TF_TILE_FLOATS;
#pragma unroll
        for (int ks = 0; ks < 4; ks++) {
            const int kb = ks * 8 + tig;
            uint32_t Afh[2][4], Afl[2][4];
#pragma unroll
            for (int mf = 0; mf < 2; mf++) {
                const int r = (ar + mf * 16) * TF_ST;
                Afh[mf][0] = __float_as_uint(sAh[r + kb]);
                Afh[mf][1] = __float_as_uint(sAh[r + 8 * TF_ST + kb]);
                Afh[mf][2] = __float_as_uint(sAh[r + kb + 4]);
                Afh[mf][3] = __float_as_uint(sAh[r + 8 * TF_ST + kb + 4]);
                Afl[mf][0] = __float_as_uint(sAl[r + kb]);
                Afl[mf][1] = __float_as_uint(sAl[r + 8 * TF_ST + kb]);
                Afl[mf][2] = __float_as_uint(sAl[r + kb + 4]);
                Afl[mf][3] = __float_as_uint(sAl[r + 8 * TF_ST + kb + 4]);
            }
#pragma unroll
            for (int nf = 0; nf < 8; nf++) {
                const int r = (br + nf * 8) * TF_ST;
                uint32_t bh0 = __float_as_uint(sBh[r + kb]);
                uint32_t bh1 = __float_as_uint(sBh[r + kb + 4]);
                uint32_t bl0 = __float_as_uint(sBl[r + kb]);
                uint32_t bl1 = __float_as_uint(sBl[r + kb + 4]);
#pragma unroll
                for (int mf = 0; mf < 2; mf++) {
                    mma_tf32(acc[mf][nf], Afh[mf], bh0, bh1);
                    mma_tf32(acc[mf][nf], Afl[mf], bh0, bh1);
                    mma_tf32(acc[mf][nf], Afh[mf], bl0, bl1);
                }
            }
        }
        if (more) cp_wait0();
        __syncthreads();
    }

#pragma unroll
    for (int mf = 0; mf < 2; mf++) {
        const int row = bm + wm * 32 + mf * 16 + grp;
#pragma unroll
        for (int nf = 0; nf < 8; nf++) {
            const int col = bn + wn * 64 + nf * 8 + tig * 2;
            float b0 = 0.f, b1 = 0.f;
            if (bias) { b0 = bias[col]; b1 = bias[col + 1]; }
            *reinterpret_cast<float2*>(C + (size_t)row * ldc + col) =
                make_float2(acc[mf][nf][0] + b0, acc[mf][nf][1] + b1);
            *reinterpret_cast<float2*>(C + (size_t)(row + 8) * ldc + col) =
                make_float2(acc[mf][nf][2] + b0, acc[mf][nf][3] + b1);
        }
    }
}

// ================================================================
// bf16-split HMMA GEMM — cp.async pipeline on pre-split operands
// ================================================================
__device__ __forceinline__ void mma16816(float* d, const uint32_t* a, const uint32_t* b) {
    asm volatile(
        "mma.sync.aligned.m16n8k16.row.col.f32.bf16.bf16.f32 "
        "{%0,%1,%2,%3}, {%4,%5,%6,%7}, {%8,%9}, {%0,%1,%2,%3};"
        : "+f"(d[0]), "+f"(d[1]), "+f"(d[2]), "+f"(d[3])
        : "r"(a[0]), "r"(a[1]), "r"(a[2]), "r"(a[3]), "r"(b[0]), "r"(b[1]));
}
__device__ __forceinline__ void ldsm_x4(uint32_t* r, uint32_t addr) {
    asm volatile("ldmatrix.sync.aligned.m8n8.x4.shared.b16 {%0,%1,%2,%3}, [%4];"
                 : "=r"(r[0]), "=r"(r[1]), "=r"(r[2]), "=r"(r[3]) : "r"(addr));
}

#define TILE_BYTES 16384
#define STAGE_BYTES (4 * TILE_BYTES)
#define GEMM_SMEM  (2 * STAGE_BYTES + 1024)

// tile: 128 rows x 64 bf16 (128B/row), SW128 swizzled
__device__ __forceinline__ void bf_cp_tile(uint32_t sm, const __nv_bfloat16* __restrict__ src,
                                           int ld, int tid)
{
    const int row = tid >> 1;
    const int cb = (tid & 1) * 4;
    const __nv_bfloat16* s = src + (size_t)row * ld + cb * 8;
#pragma unroll
    for (int j = 0; j < 4; j++) {
        uint32_t off = sw128((uint32_t)(row * 128 + (cb + j) * 16));
        cp16(sm + off, s + j * 8);
    }
}

template<int ACT>   // 0 = none, 1 = gelu
__global__ void __launch_bounds__(256, 1)
bf16_gemm(const __nv_bfloat16* __restrict__ Ah0, const __nv_bfloat16* __restrict__ Al0, int lda,
          const __nv_bfloat16* __restrict__ Bh0, const __nv_bfloat16* __restrict__ Bl0, int ldb,
          float* __restrict__ C, int ldc, int K,
          const float* __restrict__ bias, float scale)
{
    extern __shared__ char dsm[];
    const uint32_t raw = smem_u32(dsm);
    const uint32_t base = (raw + 1023) & ~1023u;

    const int tid  = threadIdx.x;
    const int lane = tid & 31;
    const int wid  = tid >> 5;
    const int wm = wid & 3;
    const int wn = wid >> 2;
    const int bm = blockIdx.y * 128;
    const int bn = blockIdx.x * 128;

    const __nv_bfloat16* Ah = Ah0 + (size_t)bm * lda;
    const __nv_bfloat16* Al = Al0 + (size_t)bm * lda;
    const __nv_bfloat16* Bh = Bh0 + (size_t)bn * ldb;
    const __nv_bfloat16* Bl = Bl0 + (size_t)bn * ldb;
    const int nk = K >> 6;

    {
        const uint32_t sb = base;
        bf_cp_tile(sb,                 Ah, lda, tid);
        bf_cp_tile(sb +     TILE_BYTES, Al, lda, tid);
        bf_cp_tile(sb + 2 * TILE_BYTES, Bh, ldb, tid);
        bf_cp_tile(sb + 3 * TILE_BYTES, Bl, ldb, tid);
        cp_commit();
        cp_wait0();
        __syncthreads();
    }

    float acc[2][8][4];
#pragma unroll
    for (int i = 0; i < 2; i++)
#pragma unroll
        for (int j = 0; j < 8; j++)
#pragma unroll
            for (int t = 0; t < 4; t++) acc[i][j][t] = 0.f;

    const int a_row = wm * 32 + (lane & 15);
    const int a_kb0 = (lane >> 4) << 4;
    const int b_row0 = wn * 64 + (lane & 7) + ((lane >> 4) << 3);
    const int b_kb0 = ((lane >> 3) & 1) << 4;

    for (int kc = 0; kc < nk; kc++) {
        const int cur = kc & 1;
        const bool more = (kc + 1 < nk);
        if (more) {
            const uint32_t sb = base + (cur ^ 1) * STAGE_BYTES;
            bf_cp_tile(sb,                 Ah + (kc + 1) * 64, lda, tid);
            bf_cp_tile(sb +     TILE_BYTES, Al + (kc + 1) * 64, lda, tid);
            bf_cp_tile(sb + 2 * TILE_BYTES, Bh + (kc + 1) * 64, ldb, tid);
            bf_cp_tile(sb + 3 * TILE_BYTES, Bl + (kc + 1) * 64, ldb, tid);
            cp_commit();
        }
        const uint32_t sb = base + cur * STAGE_BYTES;
#pragma unroll
        for (int ks = 0; ks < 4; ks++) {
            uint32_t Afh[2][4], Afl[2][4];
#pragma unroll
            for (int mf = 0; mf < 2; mf++) {
                uint32_t off = sw128((uint32_t)((a_row + mf * 16) * 128 + ks * 32 + a_kb0));
                ldsm_x4(Afh[mf], sb + off);
                ldsm_x4(Afl[mf], sb + TILE_BYTES + off);
            }
#pragma unroll
            for (int nf2 = 0; nf2 < 4; nf2++) {
                uint32_t off = sw128((uint32_t)((b_row0 + nf2 * 16) * 128 + ks * 32 + b_kb0));
                uint32_t Bfh[4], Bfl[4];
                ldsm_x4(Bfh, sb + 2 * TILE_BYTES + off);
                ldsm_x4(Bfl, sb + 3 * TILE_BYTES + off);
#pragma unroll
                for (int mf = 0; mf < 2; mf++) {
                    mma16816(acc[mf][nf2 * 2 + 0], Afh[mf], Bfh + 0);
                    mma16816(acc[mf][nf2 * 2 + 1], Afh[mf], Bfh + 2);
                    mma16816(acc[mf][nf2 * 2 + 0], Afl[mf], Bfh + 0);
                    mma16816(acc[mf][nf2 * 2 + 1], Afl[mf], Bfh + 2);
                    mma16816(acc[mf][nf2 * 2 + 0], Afh[mf], Bfl + 0);
                    mma16816(acc[mf][nf2 * 2 + 1], Afh[mf], Bfl + 2);
                }
            }
        }
        if (more) cp_wait0();
        __syncthreads();
    }

#pragma unroll
    for (int mf = 0; mf < 2; mf++) {
        const int row = bm + wm * 32 + mf * 16 + (lane >> 2);
#pragma unroll
        for (int nf = 0; nf < 8; nf++) {
            const int col = bn + wn * 64 + nf * 8 + (lane & 3) * 2;
            float b0 = 0.f, b1 = 0.f;
            if (bias) { b0 = bias[col]; b1 = bias[col + 1]; }
            float v0 = acc[mf][nf][0] + b0;
            float v1 = acc[mf][nf][1] + b1;
            float v2 = acc[mf][nf][2] + b0;
            float v3 = acc[mf][nf][3] + b1;
            if (ACT == 1) {
                v0 = gelu_exact(v0); v1 = gelu_exact(v1);
                v2 = gelu_exact(v2); v3 = gelu_exact(v3);
            }
            v0 *= scale; v1 *= scale; v2 *= scale; v3 *= scale;
            *reinterpret_cast<float2*>(C + (size_t)row * ldc + col) = make_float2(v0, v1);
            *reinterpret_cast<float2*>(C + (size_t)(row + 8) * ldc + col) = make_float2(v2, v3);
        }
    }
}

// ---------------- transpose ----------------
__global__ void __launch_bounds__(256)
transpose_kernel(const float* __restrict__ src, int sld, int rows,
                 float* __restrict__ dst)
{
    __shared__ float t[32][33];
    const int bx = blockIdx.x * 32, by = blockIdx.y * 32;
    int x = bx + threadIdx.x, y = by + threadIdx.y;
#pragma unroll
    for (int i = 0; i < 32; i += 8)
        t[threadIdx.y + i][threadIdx.x] = src[(size_t)(y + i) * sld + x];
    __syncthreads();
    x = by + threadIdx.x; y = bx + threadIdx.y;
#pragma unroll
    for (int i = 0; i < 32; i += 8)
        dst[(size_t)(y + i) * rows + x] = t[threadIdx.x][threadIdx.y + i];
}

// ---------------- batchnorm ----------------
__global__ void __launch_bounds__(256)
bn_part_kernel(const float* __restrict__ q, float* __restrict__ part)
{
    const int lane32 = threadIdx.x & 31;
    const int grp = threadIdx.x >> 5;
    const int col = blockIdx.x * 32 + lane32;
    const int slice = blockIdx.y;
    const int r0 = slice * (N_TOK / 8);
    float s = 0.f, ss = 0.f;
    for (int r = grp; r < N_TOK / 8; r += 8) {
        float v = q[(size_t)(r0 + r) * DMODEL + col];
        s += v;
        ss += v * v;
    }
    __shared__ float sh_s[8][33], sh_q[8][33];
    sh_s[grp][lane32] = s;
    sh_q[grp][lane32] = ss;
    __syncthreads();
    if (grp == 0) {
        float ts = 0.f, tss = 0.f;
#pragma unroll
        for (int i = 0; i < 8; i++) { ts += sh_s[i][lane32]; tss += sh_q[i][lane32]; }
        part[(2 * slice + 0) * DMODEL + col] = ts;
        part[(2 * slice + 1) * DMODEL + col] = tss;
    }
}

__global__ void __launch_bounds__(256)
bn_final_kernel(const float* __restrict__ part,
                const float* __restrict__ gamma, const float* __restrict__ beta,
                float* __restrict__ scale, float* __restrict__ shift)
{
    const int col = blockIdx.x * 256 + threadIdx.x;
    float s = 0.f, ss = 0.f;
#pragma unroll
    for (int i = 0; i < 8; i++) {
        s  += part[(2 * i + 0) * DMODEL + col];
        ss += part[(2 * i + 1) * DMODEL + col];
    }
    float mean = s * (1.0f / N_TOK);
    float var = ss * (1.0f / N_TOK) - mean * mean;
    float rstd = rsqrtf(var + 1e-5f);
    float sc = gamma[col] * rstd;
    scale[col] = sc;
    shift[col] = beta[col] - mean * sc;
}

// normalize + tf32 split fused
__global__ void __launch_bounds__(256)
normalize_split_kernel(const float* __restrict__ q,
                       const float* __restrict__ scale, const float* __restrict__ shift,
                       float* __restrict__ qh, float* __restrict__ ql)
{
    int i = blockIdx.x * blockDim.x + threadIdx.x;
    float4 v = reinterpret_cast<const float4*>(q)[i];
    int c = (i * 4) & (DMODEL - 1);
    v.x = v.x * scale[c + 0] + shift[c + 0];
    v.y = v.y * scale[c + 1] + shift[c + 1];
    v.z = v.z * scale[c + 2] + shift[c + 2];
    v.w = v.w * scale[c + 3] + shift[c + 3];
    float4 h = make_float4(__uint_as_float(f2tf(v.x)), __uint_as_float(f2tf(v.y)),
                           __uint_as_float(f2tf(v.z)), __uint_as_float(f2tf(v.w)));
    float4 l;
    l.x = __uint_as_float(f2tf(v.x - h.x));
    l.y = __uint_as_float(f2tf(v.y - h.y));
    l.z = __uint_as_float(f2tf(v.z - h.z));
    l.w = __uint_as_float(f2tf(v.w - h.w));
    reinterpret_cast<float4*>(qh)[i] = h;
    reinterpret_cast<float4*>(ql)[i] = l;
}

// ---------------- warp-collective top-16 of 128 values ----------------
__device__ __forceinline__ void warp_top16(const float* __restrict__ row,
                                           float* __restrict__ ov, int* __restrict__ oi,
                                           int lane)
{
    float v0 = row[lane], v1 = row[lane + 32], v2 = row[lane + 64], v3 = row[lane + 96];
#pragma unroll 1
    for (int it = 0; it < 16; it++) {
        float bv = v0; int bu = 0;
        if (v1 > bv) { bv = v1; bu = 1; }
        if (v2 > bv) { bv = v2; bu = 2; }
        if (v3 > bv) { bv = v3; bu = 3; }
        int bidx = lane + (bu << 5);
#pragma unroll
        for (int off = 16; off; off >>= 1) {
            float ovv = __shfl_down_sync(0xffffffffu, bv, off);
            int oii = __shfl_down_sync(0xffffffffu, bidx, off);
            if (ovv > bv) { bv = ovv; bidx = oii; }
        }
        bv = __shfl_sync(0xffffffffu, bv, 0);
        bidx = __shfl_sync(0xffffffffu, bidx, 0);
        if (lane == 0) { ov[it] = bv; oi[it] = bidx; }
        if ((bidx & 31) == lane) {
            int u = bidx >> 5;
            if (u == 0) v0 = NEG_INF;
            else if (u == 1) v1 = NEG_INF;
            else if (u == 2) v2 = NEG_INF;
            else v3 = NEG_INF;
        }
    }
}

__global__ void __launch_bounds__(256)
topk_kernel(const float* __restrict__ s1, const float* __restrict__ s2,
            float* __restrict__ probs, int* __restrict__ eidx)
{
    const int wid = threadIdx.x >> 5;
    const int lane = threadIdx.x & 31;
    const int row = blockIdx.x * 8 + wid;
    __shared__ float tv1[8][16], tv2[8][16];
    __shared__ int ti1[8][16], ti2[8][16];

    warp_top16(s1 + (size_t)row * NSUB, tv1[wid], ti1[wid], lane);
    warp_top16(s2 + (size_t)row * NSUB, tv2[wid], ti2[wid], lane);
    __syncwarp();

    float cv[8];
#pragma unroll
    for (int t = 0; t < 8; t++) {
        int c = lane * 8 + t;
        cv[t] = tv1[wid][c >> 4] + tv2[wid][c & 15];
    }
    float fv[8]; int fi[8];
#pragma unroll 1
    for (int it = 0; it < 8; it++) {
        float bv = cv[0]; int bt = 0;
#pragma unroll
        for (int t = 1; t < 8; t++) if (cv[t] > bv) { bv = cv[t]; bt = t; }
        int bidx = lane * 8 + bt;
#pragma unroll
        for (int off = 16; off; off >>= 1) {
            float ovv = __shfl_down_sync(0xffffffffu, bv, off);
            int oii = __shfl_down_sync(0xffffffffu, bidx, off);
            if (ovv > bv) { bv = ovv; bidx = oii; }
        }
        bv = __shfl_sync(0xffffffffu, bv, 0);
        bidx = __shfl_sync(0xffffffffu, bidx, 0);
        fv[it] = bv; fi[it] = bidx;
        if ((bidx >> 3) == lane) cv[bidx & 7] = NEG_INF;
    }

    if (lane < 8) {
        float m = fv[0];
        float sum = 0.f;
#pragma unroll
        for (int i = 0; i < 8; i++) sum += expf(fv[i] - m);
        float p = expf(fv[lane] - m) / sum;
        int c = fi[lane];
        int i1 = ti1[wid][c >> 4];
        int i2 = ti2[wid][c & 15];
        probs[(size_t)row * 8 + lane] = p;
        eidx[(size_t)row * 8 + lane] = i1 * NSUB + i2;
    }
}

// ---------------- MoE: warp-per-expert; writes acc as bf16 hi/lo split ----------------
__global__ void __launch_bounds__(256)
moe_kernel(const float* __restrict__ xproj, const float* __restrict__ Hall,
           const float* __restrict__ probs, const int* __restrict__ eidx,
           __nv_bfloat16* __restrict__ acch, __nv_bfloat16* __restrict__ accl)
{
    const int n = blockIdx.x;
    const int t = threadIdx.x;
    const int lane = t & 31, w = t >> 5;
    __shared__ float part[8][DHIDDEN];

    float xpr[16];
#pragma unroll
    for (int j = 0; j < 16; j++)
        xpr[j] = xproj[(size_t)n * DHIDDEN + j * 32 + lane];

    float pa[16];
#pragma unroll
    for (int j = 0; j < 16; j++) pa[j] = 0.f;

#pragma unroll
    for (int je = 0; je < 4; je++) {
        const int s = w * 4 + je;
        const int e = eidx[n * 32 + s];
        const float* H = Hall + (size_t)e * DHIDDEN;
        float h[16];
#pragma unroll
        for (int j = 0; j < 16; j++) h[j] = H[j * 32 + lane];
        float dot = 0.f;
#pragma unroll
        for (int j = 0; j < 16; j++) dot = fmaf(xpr[j], h[j], dot);
#pragma unroll
        for (int off = 16; off; off >>= 1)
            dot += __shfl_xor_sync(0xffffffffu, dot, off);
        const float act = gelu_exact(dot) * probs[n * 32 + s];
#pragma unroll
        for (int j = 0; j < 16; j++) pa[j] = fmaf(act, h[j], pa[j]);
    }
#pragma unroll
    for (int j = 0; j < 16; j++) part[w][j * 32 + lane] = pa[j];
    __syncthreads();

    float a0 = 0.f, a1 = 0.f;
#pragma unroll
    for (int w2 = 0; w2 < 8; w2++) {
        a0 += part[w2][t];
        a1 += part[w2][t + 256];
    }
    __nv_bfloat16 h0 = __float2bfloat16(a0);
    __nv_bfloat16 h1 = __float2bfloat16(a1);
    acch[(size_t)n * DHIDDEN + t]       = h0;
    acch[(size_t)n * DHIDDEN + 256 + t] = h1;
    accl[(size_t)n * DHIDDEN + t]       = __float2bfloat16(a0 - __bfloat162float(h0));
    accl[(size_t)n * DHIDDEN + 256 + t] = __float2bfloat16(a1 - __bfloat162float(h1));
}

// ---------------- host launch ----------------
extern "C" void kernel_launch(void* const* d_in, const int* in_sizes, int n_in,
                              void* d_out, int out_size)
{
    const float* x       = (const float*)d_in[0];
    const float* Wq      = (const float*)d_in[1];
    const float* bq      = (const float*)d_in[2];
    const float* gamma   = (const float*)d_in[3];
    const float* beta    = (const float*)d_in[4];
    const float* sk1     = (const float*)d_in[5];
    const float* sk2     = (const float*)d_in[6];
    const float* latents = (const float*)d_in[7];
    const float* W1      = (const float*)d_in[8];
    const float* W2      = (const float*)d_in[9];
    float* out = (float*)d_out;

#define SYM(var, sym) void* p_##var; cudaGetSymbolAddress(&p_##var, sym);
    SYM(q, g_q) SYM(qh, g_qh) SYM(ql, g_ql)
    SYM(s1, g_s1) SYM(s2, g_s2)
    SYM(sc, g_scale) SYM(sh, g_shift) SYM(bp, g_bnpart)
    SYM(H, g_Hall) SYM(xp, g_xproj)
    SYM(pr, g_probs) SYM(ei, g_eidx)
    SYM(w1t, g_W1T) SYM(wvt, g_WvT)
    SYM(xh, g_xh) SYM(xl, g_xl)
    SYM(wqh, g_wqh) SYM(wql, g_wql)
    SYM(sk1h, g_sk1h) SYM(sk1l, g_sk1l) SYM(sk2h, g_sk2h) SYM(sk2l, g_sk2l)
    SYM(xbh, g_xbh) SYM(xbl, g_xbl)
    SYM(lath, g_lath) SYM(latl, g_latl)
    SYM(w1th, g_w1th) SYM(w1tl, g_w1tl)
    SYM(w2h, g_w2h) SYM(w2l, g_w2l)
    SYM(wvth, g_wvth) SYM(wvtl, g_wvtl)
    SYM(acch, g_acch) SYM(accl, g_accl)
#undef SYM

    cudaFuncSetAttribute(bf16_gemm<0>, cudaFuncAttributeMaxDynamicSharedMemorySize, GEMM_SMEM);
    cudaFuncSetAttribute(bf16_gemm<1>, cudaFuncAttributeMaxDynamicSharedMemorySize, GEMM_SMEM);
    cudaFuncSetAttribute(tf32_gemm, cudaFuncAttributeMaxDynamicSharedMemorySize, TF_GEMM_SMEM);

    const dim3 blk(256);
    const dim3 tblk(32, 8);

    // transposes (fp32): W1 (256x512) -> W1T (512x256); Wv (512x1024) -> WvT (1024x512)
    transpose_kernel<<<dim3(DHIDDEN / 32, DLATENT / 32), tblk>>>(W1, DHIDDEN, DLATENT, (float*)p_w1t);
    transpose_kernel<<<dim3(DMODEL / 32, DHIDDEN / 32), tblk>>>(W2 + DMODEL, 2 * DMODEL, DHIDDEN, (float*)p_wvt);

    // one-time operand splits
    split_tf32_kernel<<<(N_TOK * DMODEL / 4) / 256, blk>>>(x, (float*)p_xh, (float*)p_xl);
    split_tf32_kernel<<<(DMODEL * DMODEL / 4) / 256, blk>>>(Wq, (float*)p_wqh, (float*)p_wql);
    split_tf32_kernel<<<(NSUB * 128 / 4) / 256, blk>>>(sk1, (float*)p_sk1h, (float*)p_sk1l);
    split_tf32_kernel<<<(NSUB * 128 / 4) / 256, blk>>>(sk2, (float*)p_sk2h, (float*)p_sk2l);
    split_bf16_kernel<<<(N_TOK * DMODEL / 4) / 256, blk>>>(x, (__nv_bfloat16*)p_xbh, (__nv_bfloat16*)p_xbl);
    split_bf16_kernel<<<(NEXPERTS * DLATENT / 4) / 256, blk>>>(latents, (__nv_bfloat16*)p_lath, (__nv_bfloat16*)p_latl);
    split_bf16_kernel<<<(DHIDDEN * DLATENT / 4) / 256, blk>>>((float*)p_w1t, (__nv_bfloat16*)p_w1th, (__nv_bfloat16*)p_w1tl);
    split_bf16_kernel<<<(DMODEL * DHIDDEN / 4) / 256, blk>>>((float*)p_wvt, (__nv_bfloat16*)p_wvth, (__nv_bfloat16*)p_wvtl);
    split_bf16_strided<<<(DHIDDEN * DMODEL / 4) / 256, blk>>>(W2, 2 * DMODEL, DMODEL / 4,
                                                              (__nv_bfloat16*)p_w2h, (__nv_bfloat16*)p_w2l);

    // 1) q = x @ Wq^T + bq   (3xTF32)
    tf32_gemm<<<dim3(DMODEL / 128, N_TOK / 128), blk, TF_GEMM_SMEM>>>(
        (float*)p_xh, (float*)p_xl, DMODEL, (float*)p_wqh, (float*)p_wql, DMODEL,
        (float*)p_q, DMODEL, DMODEL, bq);

    // 2-3) batchnorm + normalize (fused tf32 split)
    bn_part_kernel<<<dim3(DMODEL / 32, 8), blk>>>((float*)p_q, (float*)p_bp);
    bn_final_kernel<<<DMODEL / 256, blk>>>((float*)p_bp, gamma, beta, (float*)p_sc, (float*)p_sh);
    normalize_split_kernel<<<(N_TOK * DMODEL / 4) / 256, blk>>>(
        (float*)p_q, (float*)p_sc, (float*)p_sh, (float*)p_qh, (float*)p_ql);

    // 4) s1/s2 (3xTF32)
    tf32_gemm<<<dim3(1, (N_TOK * NHEADS) / 128), blk, TF_GEMM_SMEM>>>(
        (float*)p_qh, (float*)p_ql, DQUERY, (float*)p_sk1h, (float*)p_sk1l, NSUB,
        (float*)p_s1, NSUB, NSUB, nullptr);
    tf32_gemm<<<dim3(1, (N_TOK * NHEADS) / 128), blk, TF_GEMM_SMEM>>>(
        (float*)p_qh + 128, (float*)p_ql + 128, DQUERY, (float*)p_sk2h, (float*)p_sk2l, NSUB,
        (float*)p_s2, NSUB, NSUB, nullptr);

    // 5) two-level top-k
    topk_kernel<<<(N_TOK * NHEADS) / 8, blk>>>((float*)p_s1, (float*)p_s2, (float*)p_pr, (int*)p_ei);

    // 6) H_all = gelu(latents @ W1T^T)
    bf16_gemm<1><<<dim3(DHIDDEN / 128, NEXPERTS / 128), blk, GEMM_SMEM>>>(
        (__nv_bfloat16*)p_lath, (__nv_bfloat16*)p_latl, DLATENT,
        (__nv_bfloat16*)p_w1th, (__nv_bfloat16*)p_w1tl, DLATENT,
        (float*)p_H, DHIDDEN, DLATENT, nullptr, 1.0f);

    // 7) x_proj = x @ W2[:, :D]^T
    bf16_gemm<0><<<dim3(DHIDDEN / 128, N_TOK / 128), blk, GEMM_SMEM>>>(
        (__nv_bfloat16*)p_xbh, (__nv_bfloat16*)p_xbl, DMODEL,
        (__nv_bfloat16*)p_w2h, (__nv_bfloat16*)p_w2l, DMODEL,
        (float*)p_xp, DHIDDEN, DMODEL, nullptr, 1.0f);

    // 8) MoE gather / act / accumulate (writes acc bf16 split)
    moe_kernel<<<N_TOK, blk>>>((float*)p_xp, (float*)p_H, (float*)p_pr, (int*)p_ei,
                               (__nv_bfloat16*)p_acch, (__nv_bfloat16*)p_accl);

    // 9) out = acc @ WvT^T / 4
    bf16_gemm<0><<<dim3(DMODEL / 128, N_TOK / 128), blk, GEMM_SMEM>>>(
        (__nv_bfloat16*)p_acch, (__nv_bfloat16*)p_accl, DHIDDEN,
        (__nv_bfloat16*)p_wvth, (__nv_bfloat16*)p_wvtl, DHIDDEN,
        out, DMODEL, DHIDDEN, nullptr, 0.25f);
}

// round 8
// speedup vs baseline: 1.1819x; 1.1819x over previous
#include <cuda_runtime.h>
#include <cuda_bf16.h>
#include <math.h>
#include <stdint.h>

#define N_TOK        8192
#define DMODEL       1024
#define DQUERY       256
#define NHEADS       4
#define NSUB         128
#define TOPK         8
#define DLATENT      256
#define DHIDDEN      512
#define NEXPERTS     16384
#define NEG_INF      (-1.0e38f)

// ---------------- scratch (device globals; no allocation allowed) ----------------
__device__ float g_q[N_TOK * DMODEL];
__device__ float g_s1[N_TOK * NHEADS * NSUB];
__device__ float g_s2[N_TOK * NHEADS * NSUB];
__device__ float g_scale[DMODEL];
__device__ float g_shift[DMODEL];
__device__ float g_bnpart[16 * DMODEL];
__device__ float g_Hall[NEXPERTS * DHIDDEN];
__device__ float g_xproj[N_TOK * DHIDDEN];
__device__ float g_acc[N_TOK * DHIDDEN];
__device__ float g_probs[N_TOK * NHEADS * TOPK];
__device__ int   g_eidx[N_TOK * NHEADS * TOPK];
__device__ float g_W1T[DHIDDEN * DLATENT];     // 512 x 256
__device__ float g_WvT[DMODEL * DHIDDEN];      // 1024 x 512

__device__ __forceinline__ float gelu_exact(float x) {
    return 0.5f * x * (1.0f + erff(x * 0.70710678118654752f));
}

__device__ __forceinline__ uint32_t smem_u32(const void* p) {
    uint32_t a;
    asm("{ .reg .u64 t; cvta.to.shared.u64 t, %1; cvt.u32.u64 %0, t; }" : "=r"(a) : "l"(p));
    return a;
}
__device__ __forceinline__ uint32_t sw128(uint32_t o) { return o ^ ((o >> 3) & 0x70); }

// ================================================================
// 3xTF32 tensor-core GEMM (scoring path) — reg-staged pipeline
// BK=16, row pad 20 floats -> 83 KB smem -> 2 CTAs/SM
// ================================================================
__device__ __forceinline__ uint32_t f2tf(float x) {
    uint32_t u;
    asm("cvt.rna.tf32.f32 %0, %1;" : "=r"(u) : "f"(x));
    return u;
}
__device__ __forceinline__ void mma_tf32(float* d, const uint32_t* a, uint32_t b0, uint32_t b1) {
    asm volatile(
        "mma.sync.aligned.m16n8k8.row.col.f32.tf32.tf32.f32 "
        "{%0,%1,%2,%3}, {%4,%5,%6,%7}, {%8,%9}, {%0,%1,%2,%3};"
        : "+f"(d[0]), "+f"(d[1]), "+f"(d[2]), "+f"(d[3])
        : "r"(a[0]), "r"(a[1]), "r"(a[2]), "r"(a[3]), "r"(b0), "r"(b1));
}

#define TF_ST 20
#define TF_TILE_FLOATS (128 * TF_ST)
#define TF_TILE_BYTES  (TF_TILE_FLOATS * 4)
#define TF_STAGE_FLOATS (4 * TF_TILE_FLOATS)
#define TF_GEMM_SMEM   (2 * 4 * TF_TILE_BYTES + 1024)

// stage raw fp32 chunk (128 rows x 16 cols): 2 float4 per thread
__device__ __forceinline__ void tf_ldg(const float* __restrict__ src, int ld,
                                       float4* r, int tid)
{
    const int row = tid >> 1;
    const int c  = (tid & 1) << 3;
    r[0] = *reinterpret_cast<const float4*>(src + (size_t)row * ld + c);
    r[1] = *reinterpret_cast<const float4*>(src + (size_t)row * ld + c + 4);
}
__device__ __forceinline__ void tf_cvt_sts(const float4* r,
                                           float* __restrict__ smh,
                                           float* __restrict__ sml, int tid)
{
    const int row = tid >> 1;
    const int c  = (tid & 1) << 3;
#pragma unroll
    for (int p = 0; p < 2; p++) {
        const float4 v = r[p];
        float4 hi = make_float4(__uint_as_float(f2tf(v.x)), __uint_as_float(f2tf(v.y)),
                                __uint_as_float(f2tf(v.z)), __uint_as_float(f2tf(v.w)));
        float4 lo;
        lo.x = __uint_as_float(f2tf(v.x - hi.x));
        lo.y = __uint_as_float(f2tf(v.y - hi.y));
        lo.z = __uint_as_float(f2tf(v.z - hi.z));
        lo.w = __uint_as_float(f2tf(v.w - hi.w));
        *reinterpret_cast<float4*>(smh + row * TF_ST + c + p * 4) = hi;
        *reinterpret_cast<float4*>(sml + row * TF_ST + c + p * 4) = lo;
    }
}

__global__ void __launch_bounds__(256, 2)
tf32_gemm(const float* __restrict__ A, int lda,
          const float* __restrict__ B, int ldb,
          float* __restrict__ C, int ldc, int K,
          const float* __restrict__ bias)
{
    extern __shared__ char dsm[];
    const uint32_t raw = smem_u32(dsm);
    float* tiles = reinterpret_cast<float*>(dsm + (((raw + 1023) & ~1023u) - raw));

    const int tid  = threadIdx.x;
    const int lane = tid & 31;
    const int wid  = tid >> 5;
    const int wm = wid & 3;
    const int wn = wid >> 2;
    const int grp = lane >> 2;
    const int tig = lane & 3;
    const int bm = blockIdx.y * 128;
    const int bn = blockIdx.x * 128;

    const float* Ap = A + (size_t)bm * lda;
    const float* Bp = B + (size_t)bn * ldb;
    const int nk = K >> 4;

    float4 ra[2], rb[2];
    tf_ldg(Ap, lda, ra, tid);
    tf_ldg(Bp, ldb, rb, tid);
    tf_cvt_sts(ra, tiles, tiles + TF_TILE_FLOATS, tid);
    tf_cvt_sts(rb, tiles + 2 * TF_TILE_FLOATS, tiles + 3 * TF_TILE_FLOATS, tid);
    __syncthreads();

    float acc[2][8][4];
#pragma unroll
    for (int i = 0; i < 2; i++)
#pragma unroll
        for (int j = 0; j < 8; j++)
#pragma unroll
            for (int t = 0; t < 4; t++) acc[i][j][t] = 0.f;

    const int ar = wm * 32 + grp;
    const int br = wn * 64 + grp;

    for (int kc = 0; kc < nk; kc++) {
        const int cur = kc & 1;
        const bool more = (kc + 1 < nk);
        if (more) {
            tf_ldg(Ap + (kc + 1) * 16, lda, ra, tid);
            tf_ldg(Bp + (kc + 1) * 16, ldb, rb, tid);
        }
        const float* sAh = tiles + cur * TF_STAGE_FLOATS;
        const float* sAl = sAh + TF_TILE_FLOATS;
        const float* sBh = sAl + TF_TILE_FLOATS;
        const float* sBl = sBh + TF_TILE_FLOATS;
#pragma unroll
        for (int ks = 0; ks < 2; ks++) {
            const int kb = ks * 8 + tig;
            uint32_t Ah[2][4], Al[2][4];
#pragma unroll
            for (int mf = 0; mf < 2; mf++) {
                const int r = (ar + mf * 16) * TF_ST;
                Ah[mf][0] = __float_as_uint(sAh[r + kb]);
                Ah[mf][1] = __float_as_uint(sAh[r + 8 * TF_ST + kb]);
                Ah[mf][2] = __float_as_uint(sAh[r + kb + 4]);
                Ah[mf][3] = __float_as_uint(sAh[r + 8 * TF_ST + kb + 4]);
                Al[mf][0] = __float_as_uint(sAl[r + kb]);
                Al[mf][1] = __float_as_uint(sAl[r + 8 * TF_ST + kb]);
                Al[mf][2] = __float_as_uint(sAl[r + kb + 4]);
                Al[mf][3] = __float_as_uint(sAl[r + 8 * TF_ST + kb + 4]);
            }
#pragma unroll
            for (int nf = 0; nf < 8; nf++) {
                const int r = (br + nf * 8) * TF_ST;
                uint32_t bh0 = __float_as_uint(sBh[r + kb]);
                uint32_t bh1 = __float_as_uint(sBh[r + kb + 4]);
                uint32_t bl0 = __float_as_uint(sBl[r + kb]);
                uint32_t bl1 = __float_as_uint(sBl[r + kb + 4]);
#pragma unroll
                for (int mf = 0; mf < 2; mf++) {
                    mma_tf32(acc[mf][nf], Ah[mf], bh0, bh1);
                    mma_tf32(acc[mf][nf], Al[mf], bh0, bh1);
                    mma_tf32(acc[mf][nf], Ah[mf], bl0, bl1);
                }
            }
        }
        if (more) {
            float* st = tiles + (cur ^ 1) * TF_STAGE_FLOATS;
            tf_cvt_sts(ra, st, st + TF_TILE_FLOATS, tid);
            tf_cvt_sts(rb, st + 2 * TF_TILE_FLOATS, st + 3 * TF_TILE_FLOATS, tid);
        }
        __syncthreads();
    }

#pragma unroll
    for (int mf = 0; mf < 2; mf++) {
        const int row = bm + wm * 32 + mf * 16 + grp;
#pragma unroll
        for (int nf = 0; nf < 8; nf++) {
            const int col = bn + wn * 64 + nf * 8 + tig * 2;
            float b0 = 0.f, b1 = 0.f;
            if (bias) { b0 = bias[col]; b1 = bias[col + 1]; }
            *reinterpret_cast<float2*>(C + (size_t)row * ldc + col) =
                make_float2(acc[mf][nf][0] + b0, acc[mf][nf][1] + b1);
            *reinterpret_cast<float2*>(C + (size_t)(row + 8) * ldc + col) =
                make_float2(acc[mf][nf][2] + b0, acc[mf][nf][3] + b1);
        }
    }
}

// ================================================================
// bf16-split HMMA GEMM — reg-staged pipeline (round-6, unchanged)
// ================================================================
__device__ __forceinline__ void mma16816(float* d, const uint32_t* a, const uint32_t* b) {
    asm volatile(
        "mma.sync.aligned.m16n8k16.row.col.f32.bf16.bf16.f32 "
        "{%0,%1,%2,%3}, {%4,%5,%6,%7}, {%8,%9}, {%0,%1,%2,%3};"
        : "+f"(d[0]), "+f"(d[1]), "+f"(d[2]), "+f"(d[3])
        : "r"(a[0]), "r"(a[1]), "r"(a[2]), "r"(a[3]), "r"(b[0]), "r"(b[1]));
}
__device__ __forceinline__ void ldsm_x4(uint32_t* r, uint32_t addr) {
    asm volatile("ldmatrix.sync.aligned.m8n8.x4.shared.b16 {%0,%1,%2,%3}, [%4];"
                 : "=r"(r[0]), "=r"(r[1]), "=r"(r[2]), "=r"(r[3]) : "r"(addr));
}

#define TILE_BYTES 16384
#define STAGE_BYTES (4 * TILE_BYTES)
#define GEMM_SMEM  (2 * STAGE_BYTES + 1024)

__device__ __forceinline__ void bf_ldg(const float* __restrict__ src, int ld,
                                       float4* r, int tid)
{
    const int r0 = tid >> 4;
    const int c  = (tid & 15) << 2;
#pragma unroll
    for (int p = 0; p < 8; p++)
        r[p] = *reinterpret_cast<const float4*>(src + (size_t)(r0 + (p << 4)) * ld + c);
}
__device__ __forceinline__ void bf_cvt_sts(const float4* r,
                                           char* __restrict__ sm_hi,
                                           char* __restrict__ sm_lo, int tid)
{
    const int r0 = tid >> 4;
    const int c  = (tid & 15) << 2;
#pragma unroll
    for (int p = 0; p < 8; p++) {
        const int row = r0 + (p << 4);
        const float4 v = r[p];
        __nv_bfloat16 h0 = __float2bfloat16(v.x);
        __nv_bfloat16 h1 = __float2bfloat16(v.y);
        __nv_bfloat16 h2 = __float2bfloat16(v.z);
        __nv_bfloat16 h3 = __float2bfloat16(v.w);
        __nv_bfloat16 l0 = __float2bfloat16(v.x - __bfloat162float(h0));
        __nv_bfloat16 l1 = __float2bfloat16(v.y - __bfloat162float(h1));
        __nv_bfloat16 l2 = __float2bfloat16(v.z - __bfloat162float(h2));
        __nv_bfloat16 l3 = __float2bfloat16(v.w - __bfloat162float(h3));
        uint32_t hi01 = ((uint32_t)__bfloat16_as_ushort(h1) << 16) | __bfloat16_as_ushort(h0);
        uint32_t hi23 = ((uint32_t)__bfloat16_as_ushort(h3) << 16) | __bfloat16_as_ushort(h2);
        uint32_t lo01 = ((uint32_t)__bfloat16_as_ushort(l1) << 16) | __bfloat16_as_ushort(l0);
        uint32_t lo23 = ((uint32_t)__bfloat16_as_ushort(l3) << 16) | __bfloat16_as_ushort(l2);
        const uint32_t off = sw128((uint32_t)(row * 128 + (c << 1)));
        *reinterpret_cast<uint2*>(sm_hi + off) = make_uint2(hi01, hi23);
        *reinterpret_cast<uint2*>(sm_lo + off) = make_uint2(lo01, lo23);
    }
}

template<int ACT>   // 0 = none, 1 = gelu
__global__ void __launch_bounds__(256, 1)
mma_gemm(const float* __restrict__ A, int lda,
         const float* __restrict__ B, int ldb,
         float* __restrict__ C, int ldc, int K,
         const float* __restrict__ bias, float scale)
{
    extern __shared__ char dsm[];
    const uint32_t raw = smem_u32(dsm);
    const uint32_t base = (raw + 1023) & ~1023u;
    char* tiles = dsm + (base - raw);

    const int tid  = threadIdx.x;
    const int lane = tid & 31;
    const int wid  = tid >> 5;
    const int wm = wid & 3;
    const int wn = wid >> 2;
    const int bm = blockIdx.y * 128;
    const int bn = blockIdx.x * 128;

    const float* Ap = A + (size_t)bm * lda;
    const float* Bp = B + (size_t)bn * ldb;
    const int nk = K >> 6;

    float4 ra[8], rb[8];
    bf_ldg(Ap, lda, ra, tid);
    bf_ldg(Bp, ldb, rb, tid);
    bf_cvt_sts(ra, tiles, tiles + TILE_BYTES, tid);
    bf_cvt_sts(rb, tiles + 2 * TILE_BYTES, tiles + 3 * TILE_BYTES, tid);
    __syncthreads();

    float acc[2][8][4];
#pragma unroll
    for (int i = 0; i < 2; i++)
#pragma unroll
        for (int j = 0; j < 8; j++)
#pragma unroll
            for (int t = 0; t < 4; t++) acc[i][j][t] = 0.f;

    const int a_row = wm * 32 + (lane & 15);
    const int a_kb0 = (lane >> 4) << 4;
    const int b_row0 = wn * 64 + (lane & 7) + ((lane >> 4) << 3);
    const int b_kb0 = ((lane >> 3) & 1) << 4;

    for (int kc = 0; kc < nk; kc++) {
        const int cur = kc & 1;
        const bool more = (kc + 1 < nk);
        if (more) {
            bf_ldg(Ap + (kc + 1) * 64, lda, ra, tid);
            bf_ldg(Bp + (kc + 1) * 64, ldb, rb, tid);
        }
        const uint32_t sb = base + cur * STAGE_BYTES;
#pragma unroll
        for (int ks = 0; ks < 4; ks++) {
            uint32_t Ah[2][4], Al[2][4];
#pragma unroll
            for (int mf = 0; mf < 2; mf++) {
                uint32_t off = sw128((uint32_t)((a_row + mf * 16) * 128 + ks * 32 + a_kb0));
                ldsm_x4(Ah[mf], sb + off);
                ldsm_x4(Al[mf], sb + TILE_BYTES + off);
            }
#pragma unroll
            for (int nf2 = 0; nf2 < 4; nf2++) {
                uint32_t off = sw128((uint32_t)((b_row0 + nf2 * 16) * 128 + ks * 32 + b_kb0));
                uint32_t Bh[4], Bl[4];
                ldsm_x4(Bh, sb + 2 * TILE_BYTES + off);
                ldsm_x4(Bl, sb + 3 * TILE_BYTES + off);
#pragma unroll
                for (int mf = 0; mf < 2; mf++) {
                    mma16816(acc[mf][nf2 * 2 + 0], Ah[mf], Bh + 0);
                    mma16816(acc[mf][nf2 * 2 + 1], Ah[mf], Bh + 2);
                    mma16816(acc[mf][nf2 * 2 + 0], Al[mf], Bh + 0);
                    mma16816(acc[mf][nf2 * 2 + 1], Al[mf], Bh + 2);
                    mma16816(acc[mf][nf2 * 2 + 0], Ah[mf], Bl + 0);
                    mma16816(acc[mf][nf2 * 2 + 1], Ah[mf], Bl + 2);
                }
            }
        }
        if (more) {
            char* st = tiles + (cur ^ 1) * STAGE_BYTES;
            bf_cvt_sts(ra, st, st + TILE_BYTES, tid);
            bf_cvt_sts(rb, st + 2 * TILE_BYTES, st + 3 * TILE_BYTES, tid);
        }
        __syncthreads();
    }

#pragma unroll
    for (int mf = 0; mf < 2; mf++) {
        const int row = bm + wm * 32 + mf * 16 + (lane >> 2);
#pragma unroll
        for (int nf = 0; nf < 8; nf++) {
            const int col = bn + wn * 64 + nf * 8 + (lane & 3) * 2;
            float b0 = 0.f, b1 = 0.f;
            if (bias) { b0 = bias[col]; b1 = bias[col + 1]; }
            float v0 = acc[mf][nf][0] + b0;
            float v1 = acc[mf][nf][1] + b1;
            float v2 = acc[mf][nf][2] + b0;
            float v3 = acc[mf][nf][3] + b1;
            if (ACT == 1) {
                v0 = gelu_exact(v0); v1 = gelu_exact(v1);
                v2 = gelu_exact(v2); v3 = gelu_exact(v3);
            }
            v0 *= scale; v1 *= scale; v2 *= scale; v3 *= scale;
            *reinterpret_cast<float2*>(C + (size_t)row * ldc + col) = make_float2(v0, v1);
            *reinterpret_cast<float2*>(C + (size_t)(row + 8) * ldc + col) = make_float2(v2, v3);
        }
    }
}

// ---------------- transpose ----------------
__global__ void __launch_bounds__(256)
transpose_kernel(const float* __restrict__ src, int sld, int rows,
                 float* __restrict__ dst)
{
    __shared__ float t[32][33];
    const int bx = blockIdx.x * 32, by = blockIdx.y * 32;
    int x = bx + threadIdx.x, y = by + threadIdx.y;
#pragma unroll
    for (int i = 0; i < 32; i += 8)
        t[threadIdx.y + i][threadIdx.x] = src[(size_t)(y + i) * sld + x];
    __syncthreads();
    x = by + threadIdx.x; y = bx + threadIdx.y;
#pragma unroll
    for (int i = 0; i < 32; i += 8)
        dst[(size_t)(y + i) * rows + x] = t[threadIdx.x][threadIdx.y + i];
}

// ---------------- batchnorm: partial stats, then finalize ----------------
__global__ void __launch_bounds__(256)
bn_part_kernel(const float* __restrict__ q, float* __restrict__ part)
{
    const int lane32 = threadIdx.x & 31;
    const int grp = threadIdx.x >> 5;
    const int col = blockIdx.x * 32 + lane32;
    const int slice = blockIdx.y;
    const int r0 = slice * (N_TOK / 8);
    float s = 0.f, ss = 0.f;
    for (int r = grp; r < N_TOK / 8; r += 8) {
        float v = q[(size_t)(r0 + r) * DMODEL + col];
        s += v;
        ss += v * v;
    }
    __shared__ float sh_s[8][33], sh_q[8][33];
    sh_s[grp][lane32] = s;
    sh_q[grp][lane32] = ss;
    __syncthreads();
    if (grp == 0) {
        float ts = 0.f, tss = 0.f;
#pragma unroll
        for (int i = 0; i < 8; i++) { ts += sh_s[i][lane32]; tss += sh_q[i][lane32]; }
        part[(2 * slice + 0) * DMODEL + col] = ts;
        part[(2 * slice + 1) * DMODEL + col] = tss;
    }
}

__global__ void __launch_bounds__(256)
bn_final_kernel(const float* __restrict__ part,
                const float* __restrict__ gamma, const float* __restrict__ beta,
                float* __restrict__ scale, float* __restrict__ shift)
{
    const int col = blockIdx.x * 256 + threadIdx.x;
    float s = 0.f, ss = 0.f;
#pragma unroll
    for (int i = 0; i < 8; i++) {
        s  += part[(2 * i + 0) * DMODEL + col];
        ss += part[(2 * i + 1) * DMODEL + col];
    }
    float mean = s * (1.0f / N_TOK);
    float var = ss * (1.0f / N_TOK) - mean * mean;
    float rstd = rsqrtf(var + 1e-5f);
    float sc = gamma[col] * rstd;
    scale[col] = sc;
    shift[col] = beta[col] - mean * sc;
}

__global__ void __launch_bounds__(256)
normalize_kernel(float* __restrict__ q,
                 const float* __restrict__ scale, const float* __restrict__ shift)
{
    int i = blockIdx.x * blockDim.x + threadIdx.x;
    float4* q4 = reinterpret_cast<float4*>(q);
    float4 v = q4[i];
    int c = (i * 4) & (DMODEL - 1);
    v.x = v.x * scale[c + 0] + shift[c + 0];
    v.y = v.y * scale[c + 1] + shift[c + 1];
    v.z = v.z * scale[c + 2] + shift[c + 2];
    v.w = v.w * scale[c + 3] + shift[c + 3];
    q4[i] = v;
}

// ---------------- warp-collective top-16 of 128 values ----------------
__device__ __forceinline__ void warp_top16(const float* __restrict__ row,
                                           float* __restrict__ ov, int* __restrict__ oi,
                                           int lane)
{
    float v0 = row[lane], v1 = row[lane + 32], v2 = row[lane + 64], v3 = row[lane + 96];
#pragma unroll 1
    for (int it = 0; it < 16; it++) {
        float bv = v0; int bu = 0;
        if (v1 > bv) { bv = v1; bu = 1; }
        if (v2 > bv) { bv = v2; bu = 2; }
        if (v3 > bv) { bv = v3; bu = 3; }
        int bidx = lane + (bu << 5);
#pragma unroll
        for (int off = 16; off; off >>= 1) {
            float ovv = __shfl_down_sync(0xffffffffu, bv, off);
            int oii = __shfl_down_sync(0xffffffffu, bidx, off);
            if (ovv > bv) { bv = ovv; bidx = oii; }
        }
        bv = __shfl_sync(0xffffffffu, bv, 0);
        bidx = __shfl_sync(0xffffffffu, bidx, 0);
        if (lane == 0) { ov[it] = bv; oi[it] = bidx; }
        if ((bidx & 31) == lane) {
            int u = bidx >> 5;
            if (u == 0) v0 = NEG_INF;
            else if (u == 1) v1 = NEG_INF;
            else if (u == 2) v2 = NEG_INF;
            else v3 = NEG_INF;
        }
    }
}

__global__ void __launch_bounds__(256)
topk_kernel(const float* __restrict__ s1, const float* __restrict__ s2,
            float* __restrict__ probs, int* __restrict__ eidx)
{
    const int wid = threadIdx.x >> 5;
    const int lane = threadIdx.x & 31;
    const int row = blockIdx.x * 8 + wid;
    __shared__ float tv1[8][16], tv2[8][16];
    __shared__ int ti1[8][16], ti2[8][16];

    warp_top16(s1 + (size_t)row * NSUB, tv1[wid], ti1[wid], lane);
    warp_top16(s2 + (size_t)row * NSUB, tv2[wid], ti2[wid], lane);
    __syncwarp();

    float cv[8];
#pragma unroll
    for (int t = 0; t < 8; t++) {
        int c = lane * 8 + t;
        cv[t] = tv1[wid][c >> 4] + tv2[wid][c & 15];
    }
    float fv[8]; int fi[8];
#pragma unroll 1
    for (int it = 0; it < 8; it++) {
        float bv = cv[0]; int bt = 0;
#pragma unroll
        for (int t = 1; t < 8; t++) if (cv[t] > bv) { bv = cv[t]; bt = t; }
        int bidx = lane * 8 + bt;
#pragma unroll
        for (int off = 16; off; off >>= 1) {
            float ovv = __shfl_down_sync(0xffffffffu, bv, off);
            int oii = __shfl_down_sync(0xffffffffu, bidx, off);
            if (ovv > bv) { bv = ovv; bidx = oii; }
        }
        bv = __shfl_sync(0xffffffffu, bv, 0);
        bidx = __shfl_sync(0xffffffffu, bidx, 0);
        fv[it] = bv; fi[it] = bidx;
        if ((bidx >> 3) == lane) cv[bidx & 7] = NEG_INF;
    }

    if (lane < 8) {
        float m = fv[0];
        float sum = 0.f;
#pragma unroll
        for (int i = 0; i < 8; i++) sum += expf(fv[i] - m);
        float p = expf(fv[lane] - m) / sum;
        int c = fi[lane];
        int i1 = ti1[wid][c >> 4];
        int i2 = ti2[wid][c & 15];
        probs[(size_t)row * 8 + lane] = p;
        eidx[(size_t)row * 8 + lane] = i1 * NSUB + i2;
    }
}

// ---------------- MoE per-token: warp-per-expert, sync-free mainloop ----------------
__global__ void __launch_bounds__(256)
moe_kernel(const float* __restrict__ xproj, const float* __restrict__ Hall,
           const float* __restrict__ probs, const int* __restrict__ eidx,
           float* __restrict__ accb)
{
    const int n = blockIdx.x;
    const int t = threadIdx.x;
    const int lane = t & 31, w = t >> 5;
    __shared__ float part[8][DHIDDEN];

    float xpr[16];
#pragma unroll
    for (int j = 0; j < 16; j++)
        xpr[j] = xproj[(size_t)n * DHIDDEN + j * 32 + lane];

    float pa[16];
#pragma unroll
    for (int j = 0; j < 16; j++) pa[j] = 0.f;

#pragma unroll
    for (int je = 0; je < 4; je++) {
        const int s = w * 4 + je;
        const int e = eidx[n * 32 + s];
        const float* H = Hall + (size_t)e * DHIDDEN;
        float h[16];
#pragma unroll
        for (int j = 0; j < 16; j++) h[j] = H[j * 32 + lane];
        float dot = 0.f;
#pragma unroll
        for (int j = 0; j < 16; j++) dot = fmaf(xpr[j], h[j], dot);
#pragma unroll
        for (int off = 16; off; off >>= 1)
            dot += __shfl_xor_sync(0xffffffffu, dot, off);
        const float act = gelu_exact(dot) * probs[n * 32 + s];
#pragma unroll
        for (int j = 0; j < 16; j++) pa[j] = fmaf(act, h[j], pa[j]);
    }
#pragma unroll
    for (int j = 0; j < 16; j++) part[w][j * 32 + lane] = pa[j];
    __syncthreads();

    float a0 = 0.f, a1 = 0.f;
#pragma unroll
    for (int w2 = 0; w2 < 8; w2++) {
        a0 += part[w2][t];
        a1 += part[w2][t + 256];
    }
    accb[(size_t)n * DHIDDEN + t] = a0;
    accb[(size_t)n * DHIDDEN + 256 + t] = a1;
}

// ---------------- host launch ----------------
extern "C" void kernel_launch(void* const* d_in, const int* in_sizes, int n_in,
                              void* d_out, int out_size)
{
    const float* x       = (const float*)d_in[0];
    const float* Wq      = (const float*)d_in[1];
    const float* bq      = (const float*)d_in[2];
    const float* gamma   = (const float*)d_in[3];
    const float* beta    = (const float*)d_in[4];
    const float* sk1     = (const float*)d_in[5];
    const float* sk2     = (const float*)d_in[6];
    const float* latents = (const float*)d_in[7];
    const float* W1      = (const float*)d_in[8];
    const float* W2      = (const float*)d_in[9];
    float* out = (float*)d_out;

    void *pq, *ps1, *ps2, *psc, *psh, *pbp, *pH, *pxp, *pacc, *ppr, *pei, *pw1t, *pwvt;
    cudaGetSymbolAddress(&pq, g_q);
    cudaGetSymbolAddress(&ps1, g_s1);
    cudaGetSymbolAddress(&ps2, g_s2);
    cudaGetSymbolAddress(&psc, g_scale);
    cudaGetSymbolAddress(&psh, g_shift);
    cudaGetSymbolAddress(&pbp, g_bnpart);
    cudaGetSymbolAddress(&pH, g_Hall);
    cudaGetSymbolAddress(&pxp, g_xproj);
    cudaGetSymbolAddress(&pacc, g_acc);
    cudaGetSymbolAddress(&ppr, g_probs);
    cudaGetSymbolAddress(&pei, g_eidx);
    cudaGetSymbolAddress(&pw1t, g_W1T);
    cudaGetSymbolAddress(&pwvt, g_WvT);

    float* q_buf   = (float*)pq;
    float* s1_buf  = (float*)ps1;
    float* s2_buf  = (float*)ps2;
    float* sc_buf  = (float*)psc;
    float* sh_buf  = (float*)psh;
    float* bp_buf  = (float*)pbp;
    float* H_buf   = (float*)pH;
    float* xp_buf  = (float*)pxp;
    float* acc_buf = (float*)pacc;
    float* pr_buf  = (float*)ppr;
    int*   ei_buf  = (int*)pei;
    float* w1t_buf = (float*)pw1t;
    float* wvt_buf = (float*)pwvt;

    cudaFuncSetAttribute(mma_gemm<0>, cudaFuncAttributeMaxDynamicSharedMemorySize, GEMM_SMEM);
    cudaFuncSetAttribute(mma_gemm<1>, cudaFuncAttributeMaxDynamicSharedMemorySize, GEMM_SMEM);
    cudaFuncSetAttribute(tf32_gemm, cudaFuncAttributeMaxDynamicSharedMemorySize, TF_GEMM_SMEM);

    const dim3 blk(256);
    const dim3 tblk(32, 8);

    transpose_kernel<<<dim3(DHIDDEN / 32, DLATENT / 32), tblk>>>(W1, DHIDDEN, DLATENT, w1t_buf);
    transpose_kernel<<<dim3(DMODEL / 32, DHIDDEN / 32), tblk>>>(W2 + DMODEL, 2 * DMODEL, DHIDDEN, wvt_buf);

    // 1) q = x @ Wq^T + bq   (3xTF32, 2 CTAs/SM)
    tf32_gemm<<<dim3(DMODEL / 128, N_TOK / 128), blk, TF_GEMM_SMEM>>>(
        x, DMODEL, Wq, DMODEL, q_buf, DMODEL, DMODEL, bq);

    // 2-3) batchnorm
    bn_part_kernel<<<dim3(DMODEL / 32, 8), blk>>>(q_buf, bp_buf);
    bn_final_kernel<<<DMODEL / 256, blk>>>(bp_buf, gamma, beta, sc_buf, sh_buf);
    normalize_kernel<<<(N_TOK * DMODEL / 4) / 256, blk>>>(q_buf, sc_buf, sh_buf);

    // 4) s1/s2 (3xTF32)
    tf32_gemm<<<dim3(1, (N_TOK * NHEADS) / 128), blk, TF_GEMM_SMEM>>>(
        q_buf, DQUERY, sk1, NSUB, s1_buf, NSUB, NSUB, nullptr);
    tf32_gemm<<<dim3(1, (N_TOK * NHEADS) / 128), blk, TF_GEMM_SMEM>>>(
        q_buf + 128, DQUERY, sk2, NSUB, s2_buf, NSUB, NSUB, nullptr);

    // 5) two-level top-k
    topk_kernel<<<(N_TOK * NHEADS) / 8, blk>>>(s1_buf, s2_buf, pr_buf, ei_buf);

    // 6) H_all = gelu(latents @ W1T^T)   (bf16 tensor cores)
    mma_gemm<1><<<dim3(DHIDDEN / 128, NEXPERTS / 128), blk, GEMM_SMEM>>>(
        latents, DLATENT, w1t_buf, DLATENT, H_buf, DHIDDEN, DLATENT, nullptr, 1.0f);

    // 7) x_proj = x @ W2[:, :D]^T   (bf16 tensor cores)
    mma_gemm<0><<<dim3(DHIDDEN / 128, N_TOK / 128), blk, GEMM_SMEM>>>(
        x, DMODEL, W2, 2 * DMODEL, xp_buf, DHIDDEN, DMODEL, nullptr, 1.0f);

    // 8) MoE gather / act / accumulate
    moe_kernel<<<N_TOK, blk>>>(xp_buf, H_buf, pr_buf, ei_buf, acc_buf);

    // 9) out = acc @ WvT^T / 4   (bf16 tensor cores)
    mma_gemm<0><<<dim3(DMODEL / 128, N_TOK / 128), blk, GEMM_SMEM>>>(
        acc_buf, DHIDDEN, wvt_buf, DHIDDEN, out, DMODEL, DHIDDEN, nullptr, 0.25f);
}

// round 9
// speedup vs baseline: 1.1959x; 1.0119x over previous
#include <cuda_runtime.h>
#include <cuda_bf16.h>
#include <math.h>
#include <stdint.h>

#define N_TOK        8192
#define DMODEL       1024
#define DQUERY       256
#define NHEADS       4
#define NSUB         128
#define TOPK         8
#define DLATENT      256
#define DHIDDEN      512
#define NEXPERTS     16384
#define NEG_INF      (-1.0e38f)

// ---------------- scratch (device globals; no allocation allowed) ----------------
__device__ float g_q[N_TOK * DMODEL];
__device__ float g_s1[N_TOK * NHEADS * NSUB];
__device__ float g_s2[N_TOK * NHEADS * NSUB];
__device__ float g_scale[DMODEL];
__device__ float g_shift[DMODEL];
__device__ float g_bnpart[16 * DMODEL];
__device__ float g_Hall[NEXPERTS * DHIDDEN];
__device__ float g_xproj[N_TOK * DHIDDEN];
__device__ float g_acc[N_TOK * DHIDDEN];
__device__ float g_probs[N_TOK * NHEADS * TOPK];
__device__ int   g_eidx[N_TOK * NHEADS * TOPK];
__device__ float g_W1T[DHIDDEN * DLATENT];     // 512 x 256
__device__ float g_WvT[DMODEL * DHIDDEN];      // 1024 x 512

__device__ __forceinline__ float gelu_exact(float x) {
    return 0.5f * x * (1.0f + erff(x * 0.70710678118654752f));
}

__device__ __forceinline__ uint32_t smem_u32(const void* p) {
    uint32_t a;
    asm("{ .reg .u64 t; cvta.to.shared.u64 t, %1; cvt.u32.u64 %0, t; }" : "=r"(a) : "l"(p));
    return a;
}
__device__ __forceinline__ uint32_t sw128(uint32_t o) { return o ^ ((o >> 3) & 0x70); }

// ================================================================
// 3xTF32 tensor-core GEMM (scoring path) — reg-staged pipeline,
// term-major MMA ordering (per-acc order unchanged -> bit-identical)
// ================================================================
__device__ __forceinline__ uint32_t f2tf(float x) {
    uint32_t u;
    asm("cvt.rna.tf32.f32 %0, %1;" : "=r"(u) : "f"(x));
    return u;
}
__device__ __forceinline__ void mma_tf32(float* d, const uint32_t* a, uint32_t b0, uint32_t b1) {
    asm volatile(
        "mma.sync.aligned.m16n8k8.row.col.f32.tf32.tf32.f32 "
        "{%0,%1,%2,%3}, {%4,%5,%6,%7}, {%8,%9}, {%0,%1,%2,%3};"
        : "+f"(d[0]), "+f"(d[1]), "+f"(d[2]), "+f"(d[3])
        : "r"(a[0]), "r"(a[1]), "r"(a[2]), "r"(a[3]), "r"(b0), "r"(b1));
}

#define TF_ST 36
#define TF_TILE_FLOATS (128 * TF_ST)
#define TF_TILE_BYTES  (TF_TILE_FLOATS * 4)
#define TF_STAGE_FLOATS (4 * TF_TILE_FLOATS)
#define TF_GEMM_SMEM   (2 * 4 * TF_TILE_BYTES + 1024)

__device__ __forceinline__ void tf_ldg(const float* __restrict__ src, int ld,
                                       float4* r, int tid)
{
    const int r0 = tid >> 3;
    const int c  = (tid & 7) << 2;
#pragma unroll
    for (int p = 0; p < 4; p++)
        r[p] = *reinterpret_cast<const float4*>(src + (size_t)(r0 + (p << 5)) * ld + c);
}
__device__ __forceinline__ void tf_cvt_sts(const float4* r,
                                           float* __restrict__ smh,
                                           float* __restrict__ sml, int tid)
{
    const int r0 = tid >> 3;
    const int c  = (tid & 7) << 2;
#pragma unroll
    for (int p = 0; p < 4; p++) {
        const int row = r0 + (p << 5);
        const float4 v = r[p];
        float4 hi = make_float4(__uint_as_float(f2tf(v.x)), __uint_as_float(f2tf(v.y)),
                                __uint_as_float(f2tf(v.z)), __uint_as_float(f2tf(v.w)));
        float4 lo;
        lo.x = __uint_as_float(f2tf(v.x - hi.x));
        lo.y = __uint_as_float(f2tf(v.y - hi.y));
        lo.z = __uint_as_float(f2tf(v.z - hi.z));
        lo.w = __uint_as_float(f2tf(v.w - hi.w));
        *reinterpret_cast<float4*>(smh + row * TF_ST + c) = hi;
        *reinterpret_cast<float4*>(sml + row * TF_ST + c) = lo;
    }
}

__global__ void __launch_bounds__(256, 1)
tf32_gemm(const float* __restrict__ A, int lda,
          const float* __restrict__ B, int ldb,
          float* __restrict__ C, int ldc, int K,
          const float* __restrict__ bias)
{
    extern __shared__ char dsm[];
    const uint32_t raw = smem_u32(dsm);
    float* tiles = reinterpret_cast<float*>(dsm + (((raw + 1023) & ~1023u) - raw));

    const int tid  = threadIdx.x;
    const int lane = tid & 31;
    const int wid  = tid >> 5;
    const int wm = wid & 3;
    const int wn = wid >> 2;
    const int grp = lane >> 2;
    const int tig = lane & 3;
    const int bm = blockIdx.y * 128;
    const int bn = blockIdx.x * 128;

    const float* Ap = A + (size_t)bm * lda;
    const float* Bp = B + (size_t)bn * ldb;
    const int nk = K >> 5;

    float4 ra[4], rb[4];
    tf_ldg(Ap, lda, ra, tid);
    tf_ldg(Bp, ldb, rb, tid);
    tf_cvt_sts(ra, tiles, tiles + TF_TILE_FLOATS, tid);
    tf_cvt_sts(rb, tiles + 2 * TF_TILE_FLOATS, tiles + 3 * TF_TILE_FLOATS, tid);
    __syncthreads();

    float acc[2][8][4];
#pragma unroll
    for (int i = 0; i < 2; i++)
#pragma unroll
        for (int j = 0; j < 8; j++)
#pragma unroll
            for (int t = 0; t < 4; t++) acc[i][j][t] = 0.f;

    const int ar = wm * 32 + grp;
    const int br = wn * 64 + grp;

    for (int kc = 0; kc < nk; kc++) {
        const int cur = kc & 1;
        const bool more = (kc + 1 < nk);
        if (more) {
            tf_ldg(Ap + (kc + 1) * 32, lda, ra, tid);
            tf_ldg(Bp + (kc + 1) * 32, ldb, rb, tid);
        }
        const float* sAh = tiles + cur * TF_STAGE_FLOATS;
        const float* sAl = sAh + TF_TILE_FLOATS;
        const float* sBh = sAl + TF_TILE_FLOATS;
        const float* sBl = sBh + TF_TILE_FLOATS;
#pragma unroll
        for (int ks = 0; ks < 4; ks++) {
            const int kb = ks * 8 + tig;
            uint32_t Ah[2][4], Al[2][4];
#pragma unroll
            for (int mf = 0; mf < 2; mf++) {
                const int r = (ar + mf * 16) * TF_ST;
                Ah[mf][0] = __float_as_uint(sAh[r + kb]);
                Ah[mf][1] = __float_as_uint(sAh[r + 8 * TF_ST + kb]);
                Ah[mf][2] = __float_as_uint(sAh[r + kb + 4]);
                Ah[mf][3] = __float_as_uint(sAh[r + 8 * TF_ST + kb + 4]);
                Al[mf][0] = __float_as_uint(sAl[r + kb]);
                Al[mf][1] = __float_as_uint(sAl[r + 8 * TF_ST + kb]);
                Al[mf][2] = __float_as_uint(sAl[r + kb + 4]);
                Al[mf][3] = __float_as_uint(sAl[r + 8 * TF_ST + kb + 4]);
            }
            uint32_t Bh[8][2], Bl[8][2];
#pragma unroll
            for (int nf = 0; nf < 8; nf++) {
                const int r = (br + nf * 8) * TF_ST;
                Bh[nf][0] = __float_as_uint(sBh[r + kb]);
                Bh[nf][1] = __float_as_uint(sBh[r + kb + 4]);
                Bl[nf][0] = __float_as_uint(sBl[r + kb]);
                Bl[nf][1] = __float_as_uint(sBl[r + kb + 4]);
            }
            // term-major: per-accumulator order is still AhBh, AlBh, AhBl
#pragma unroll
            for (int nf = 0; nf < 8; nf++)
#pragma unroll
                for (int mf = 0; mf < 2; mf++)
                    mma_tf32(acc[mf][nf], Ah[mf], Bh[nf][0], Bh[nf][1]);
#pragma unroll
            for (int nf = 0; nf < 8; nf++)
#pragma unroll
                for (int mf = 0; mf < 2; mf++)
                    mma_tf32(acc[mf][nf], Al[mf], Bh[nf][0], Bh[nf][1]);
#pragma unroll
            for (int nf = 0; nf < 8; nf++)
#pragma unroll
                for (int mf = 0; mf < 2; mf++)
                    mma_tf32(acc[mf][nf], Ah[mf], Bl[nf][0], Bl[nf][1]);
        }
        if (more) {
            float* st = tiles + (cur ^ 1) * TF_STAGE_FLOATS;
            tf_cvt_sts(ra, st, st + TF_TILE_FLOATS, tid);
            tf_cvt_sts(rb, st + 2 * TF_TILE_FLOATS, st + 3 * TF_TILE_FLOATS, tid);
        }
        __syncthreads();
    }

#pragma unroll
    for (int mf = 0; mf < 2; mf++) {
        const int row = bm + wm * 32 + mf * 16 + grp;
#pragma unroll
        for (int nf = 0; nf < 8; nf++) {
            const int col = bn + wn * 64 + nf * 8 + tig * 2;
            float b0 = 0.f, b1 = 0.f;
            if (bias) { b0 = bias[col]; b1 = bias[col + 1]; }
            *reinterpret_cast<float2*>(C + (size_t)row * ldc + col) =
                make_float2(acc[mf][nf][0] + b0, acc[mf][nf][1] + b1);
            *reinterpret_cast<float2*>(C + (size_t)(row + 8) * ldc + col) =
                make_float2(acc[mf][nf][2] + b0, acc[mf][nf][3] + b1);
        }
    }
}

// ================================================================
// bf16-split HMMA GEMM — reg-staged pipeline, term-major ordering
// ================================================================
__device__ __forceinline__ void mma16816(float* d, const uint32_t* a, const uint32_t* b) {
    asm volatile(
        "mma.sync.aligned.m16n8k16.row.col.f32.bf16.bf16.f32 "
        "{%0,%1,%2,%3}, {%4,%5,%6,%7}, {%8,%9}, {%0,%1,%2,%3};"
        : "+f"(d[0]), "+f"(d[1]), "+f"(d[2]), "+f"(d[3])
        : "r"(a[0]), "r"(a[1]), "r"(a[2]), "r"(a[3]), "r"(b[0]), "r"(b[1]));
}
__device__ __forceinline__ void ldsm_x4(uint32_t* r, uint32_t addr) {
    asm volatile("ldmatrix.sync.aligned.m8n8.x4.shared.b16 {%0,%1,%2,%3}, [%4];"
                 : "=r"(r[0]), "=r"(r[1]), "=r"(r[2]), "=r"(r[3]) : "r"(addr));
}

#define TILE_BYTES 16384
#define STAGE_BYTES (4 * TILE_BYTES)
#define GEMM_SMEM  (2 * STAGE_BYTES + 1024)

__device__ __forceinline__ void bf_ldg(const float* __restrict__ src, int ld,
                                       float4* r, int tid)
{
    const int r0 = tid >> 4;
    const int c  = (tid & 15) << 2;
#pragma unroll
    for (int p = 0; p < 8; p++)
        r[p] = *reinterpret_cast<const float4*>(src + (size_t)(r0 + (p << 4)) * ld + c);
}
__device__ __forceinline__ void bf_cvt_sts(const float4* r,
                                           char* __restrict__ sm_hi,
                                           char* __restrict__ sm_lo, int tid)
{
    const int r0 = tid >> 4;
    const int c  = (tid & 15) << 2;
#pragma unroll
    for (int p = 0; p < 8; p++) {
        const int row = r0 + (p << 4);
        const float4 v = r[p];
        __nv_bfloat16 h0 = __float2bfloat16(v.x);
        __nv_bfloat16 h1 = __float2bfloat16(v.y);
        __nv_bfloat16 h2 = __float2bfloat16(v.z);
        __nv_bfloat16 h3 = __float2bfloat16(v.w);
        __nv_bfloat16 l0 = __float2bfloat16(v.x - __bfloat162float(h0));
        __nv_bfloat16 l1 = __float2bfloat16(v.y - __bfloat162float(h1));
        __nv_bfloat16 l2 = __float2bfloat16(v.z - __bfloat162float(h2));
        __nv_bfloat16 l3 = __float2bfloat16(v.w - __bfloat162float(h3));
        uint32_t hi01 = ((uint32_t)__bfloat16_as_ushort(h1) << 16) | __bfloat16_as_ushort(h0);
        uint32_t hi23 = ((uint32_t)__bfloat16_as_ushort(h3) << 16) | __bfloat16_as_ushort(h2);
        uint32_t lo01 = ((uint32_t)__bfloat16_as_ushort(l1) << 16) | __bfloat16_as_ushort(l0);
        uint32_t lo23 = ((uint32_t)__bfloat16_as_ushort(l3) << 16) | __bfloat16_as_ushort(l2);
        const uint32_t off = sw128((uint32_t)(row * 128 + (c << 1)));
        *reinterpret_cast<uint2*>(sm_hi + off) = make_uint2(hi01, hi23);
        *reinterpret_cast<uint2*>(sm_lo + off) = make_uint2(lo01, lo23);
    }
}

template<int ACT>   // 0 = none, 1 = gelu
__global__ void __launch_bounds__(256, 1)
mma_gemm(const float* __restrict__ A, int lda,
         const float* __restrict__ B, int ldb,
         float* __restrict__ C, int ldc, int K,
         const float* __restrict__ bias, float scale)
{
    extern __shared__ char dsm[];
    const uint32_t raw = smem_u32(dsm);
    const uint32_t base = (raw + 1023) & ~1023u;
    char* tiles = dsm + (base - raw);

    const int tid  = threadIdx.x;
    const int lane = tid & 31;
    const int wid  = tid >> 5;
    const int wm = wid & 3;
    const int wn = wid >> 2;
    const int bm = blockIdx.y * 128;
    const int bn = blockIdx.x * 128;

    const float* Ap = A + (size_t)bm * lda;
    const float* Bp = B + (size_t)bn * ldb;
    const int nk = K >> 6;

    float4 ra[8], rb[8];
    bf_ldg(Ap, lda, ra, tid);
    bf_ldg(Bp, ldb, rb, tid);
    bf_cvt_sts(ra, tiles, tiles + TILE_BYTES, tid);
    bf_cvt_sts(rb, tiles + 2 * TILE_BYTES, tiles + 3 * TILE_BYTES, tid);
    __syncthreads();

    float acc[2][8][4];
#pragma unroll
    for (int i = 0; i < 2; i++)
#pragma unroll
        for (int j = 0; j < 8; j++)
#pragma unroll
            for (int t = 0; t < 4; t++) acc[i][j][t] = 0.f;

    const int a_row = wm * 32 + (lane & 15);
    const int a_kb0 = (lane >> 4) << 4;
    const int b_row0 = wn * 64 + (lane & 7) + ((lane >> 4) << 3);
    const int b_kb0 = ((lane >> 3) & 1) << 4;

    for (int kc = 0; kc < nk; kc++) {
        const int cur = kc & 1;
        const bool more = (kc + 1 < nk);
        if (more) {
            bf_ldg(Ap + (kc + 1) * 64, lda, ra, tid);
            bf_ldg(Bp + (kc + 1) * 64, ldb, rb, tid);
        }
        const uint32_t sb = base + cur * STAGE_BYTES;
#pragma unroll
        for (int ks = 0; ks < 4; ks++) {
            uint32_t Ah[2][4], Al[2][4];
#pragma unroll
            for (int mf = 0; mf < 2; mf++) {
                uint32_t off = sw128((uint32_t)((a_row + mf * 16) * 128 + ks * 32 + a_kb0));
                ldsm_x4(Ah[mf], sb + off);
                ldsm_x4(Al[mf], sb + TILE_BYTES + off);
            }
            uint32_t Bh[4][4], Bl[4][4];
#pragma unroll
            for (int nf2 = 0; nf2 < 4; nf2++) {
                uint32_t off = sw128((uint32_t)((b_row0 + nf2 * 16) * 128 + ks * 32 + b_kb0));
                ldsm_x4(Bh[nf2], sb + 2 * TILE_BYTES + off);
                ldsm_x4(Bl[nf2], sb + 3 * TILE_BYTES + off);
            }
            // term-major: per-accumulator order is still AhBh, AlBh, AhBl
#pragma unroll
            for (int nf2 = 0; nf2 < 4; nf2++)
#pragma unroll
                for (int mf = 0; mf < 2; mf++) {
                    mma16816(acc[mf][nf2 * 2 + 0], Ah[mf], Bh[nf2] + 0);
                    mma16816(acc[mf][nf2 * 2 + 1], Ah[mf], Bh[nf2] + 2);
                }
#pragma unroll
            for (int nf2 = 0; nf2 < 4; nf2++)
#pragma unroll
                for (int mf = 0; mf < 2; mf++) {
                    mma16816(acc[mf][nf2 * 2 + 0], Al[mf], Bh[nf2] + 0);
                    mma16816(acc[mf][nf2 * 2 + 1], Al[mf], Bh[nf2] + 2);
                }
#pragma unroll
            for (int nf2 = 0; nf2 < 4; nf2++)
#pragma unroll
                for (int mf = 0; mf < 2; mf++) {
                    mma16816(acc[mf][nf2 * 2 + 0], Ah[mf], Bl[nf2] + 0);
                    mma16816(acc[mf][nf2 * 2 + 1], Ah[mf], Bl[nf2] + 2);
                }
        }
        if (more) {
            char* st = tiles + (cur ^ 1) * STAGE_BYTES;
            bf_cvt_sts(ra, st, st + TILE_BYTES, tid);
            bf_cvt_sts(rb, st + 2 * TILE_BYTES, st + 3 * TILE_BYTES, tid);
        }
        __syncthreads();
    }

#pragma unroll
    for (int mf = 0; mf < 2; mf++) {
        const int row = bm + wm * 32 + mf * 16 + (lane >> 2);
#pragma unroll
        for (int nf = 0; nf < 8; nf++) {
            const int col = bn + wn * 64 + nf * 8 + (lane & 3) * 2;
            float b0 = 0.f, b1 = 0.f;
            if (bias) { b0 = bias[col]; b1 = bias[col + 1]; }
            float v0 = acc[mf][nf][0] + b0;
            float v1 = acc[mf][nf][1] + b1;
            float v2 = acc[mf][nf][2] + b0;
            float v3 = acc[mf][nf][3] + b1;
            if (ACT == 1) {
                v0 = gelu_exact(v0); v1 = gelu_exact(v1);
                v2 = gelu_exact(v2); v3 = gelu_exact(v3);
            }
            v0 *= scale; v1 *= scale; v2 *= scale; v3 *= scale;
            *reinterpret_cast<float2*>(C + (size_t)row * ldc + col) = make_float2(v0, v1);
            *reinterpret_cast<float2*>(C + (size_t)(row + 8) * ldc + col) = make_float2(v2, v3);
        }
    }
}

// ---------------- transpose ----------------
__global__ void __launch_bounds__(256)
transpose_kernel(const float* __restrict__ src, int sld, int rows,
                 float* __restrict__ dst)
{
    __shared__ float t[32][33];
    const int bx = blockIdx.x * 32, by = blockIdx.y * 32;
    int x = bx + threadIdx.x, y = by + threadIdx.y;
#pragma unroll
    for (int i = 0; i < 32; i += 8)
        t[threadIdx.y + i][threadIdx.x] = src[(size_t)(y + i) * sld + x];
    __syncthreads();
    x = by + threadIdx.x; y = bx + threadIdx.y;
#pragma unroll
    for (int i = 0; i < 32; i += 8)
        dst[(size_t)(y + i) * rows + x] = t[threadIdx.x][threadIdx.y + i];
}

// ---------------- batchnorm: partial stats, then finalize ----------------
__global__ void __launch_bounds__(256)
bn_part_kernel(const float* __restrict__ q, float* __restrict__ part)
{
    const int lane32 = threadIdx.x & 31;
    const int grp = threadIdx.x >> 5;
    const int col = blockIdx.x * 32 + lane32;
    const int slice = blockIdx.y;
    const int r0 = slice * (N_TOK / 8);
    float s = 0.f, ss = 0.f;
    for (int r = grp; r < N_TOK / 8; r += 8) {
        float v = q[(size_t)(r0 + r) * DMODEL + col];
        s += v;
        ss += v * v;
    }
    __shared__ float sh_s[8][33], sh_q[8][33];
    sh_s[grp][lane32] = s;
    sh_q[grp][lane32] = ss;
    __syncthreads();
    if (grp == 0) {
        float ts = 0.f, tss = 0.f;
#pragma unroll
        for (int i = 0; i < 8; i++) { ts += sh_s[i][lane32]; tss += sh_q[i][lane32]; }
        part[(2 * slice + 0) * DMODEL + col] = ts;
        part[(2 * slice + 1) * DMODEL + col] = tss;
    }
}

__global__ void __launch_bounds__(256)
bn_final_kernel(const float* __restrict__ part,
                const float* __restrict__ gamma, const float* __restrict__ beta,
                float* __restrict__ scale, float* __restrict__ shift)
{
    const int col = blockIdx.x * 256 + threadIdx.x;
    float s = 0.f, ss = 0.f;
#pragma unroll
    for (int i = 0; i < 8; i++) {
        s  += part[(2 * i + 0) * DMODEL + col];
        ss += part[(2 * i + 1) * DMODEL + col];
    }
    float mean = s * (1.0f / N_TOK);
    float var = ss * (1.0f / N_TOK) - mean * mean;
    float rstd = rsqrtf(var + 1e-5f);
    float sc = gamma[col] * rstd;
    scale[col] = sc;
    shift[col] = beta[col] - mean * sc;
}

__global__ void __launch_bounds__(256)
normalize_kernel(float* __restrict__ q,
                 const float* __restrict__ scale, const float* __restrict__ shift)
{
    int i = blockIdx.x * blockDim.x + threadIdx.x;
    float4* q4 = reinterpret_cast<float4*>(q);
    float4 v = q4[i];
    int c = (i * 4) & (DMODEL - 1);
    v.x = v.x * scale[c + 0] + shift[c + 0];
    v.y = v.y * scale[c + 1] + shift[c + 1];
    v.z = v.z * scale[c + 2] + shift[c + 2];
    v.w = v.w * scale[c + 3] + shift[c + 3];
    q4[i] = v;
}

// ---------------- warp-collective top-16 of 128 values ----------------
__device__ __forceinline__ void warp_top16(const float* __restrict__ row,
                                           float* __restrict__ ov, int* __restrict__ oi,
                                           int lane)
{
    float v0 = row[lane], v1 = row[lane + 32], v2 = row[lane + 64], v3 = row[lane + 96];
#pragma unroll 1
    for (int it = 0; it < 16; it++) {
        float bv = v0; int bu = 0;
        if (v1 > bv) { bv = v1; bu = 1; }
        if (v2 > bv) { bv = v2; bu = 2; }
        if (v3 > bv) { bv = v3; bu = 3; }
        int bidx = lane + (bu << 5);
#pragma unroll
        for (int off = 16; off; off >>= 1) {
            float ovv = __shfl_down_sync(0xffffffffu, bv, off);
            int oii = __shfl_down_sync(0xffffffffu, bidx, off);
            if (ovv > bv) { bv = ovv; bidx = oii; }
        }
        bv = __shfl_sync(0xffffffffu, bv, 0);
        bidx = __shfl_sync(0xffffffffu, bidx, 0);
        if (lane == 0) { ov[it] = bv; oi[it] = bidx; }
        if ((bidx & 31) == lane) {
            int u = bidx >> 5;
            if (u == 0) v0 = NEG_INF;
            else if (u == 1) v1 = NEG_INF;
            else if (u == 2) v2 = NEG_INF;
            else v3 = NEG_INF;
        }
    }
}

__global__ void __launch_bounds__(256)
topk_kernel(const float* __restrict__ s1, const float* __restrict__ s2,
            float* __restrict__ probs, int* __restrict__ eidx)
{
    const int wid = threadIdx.x >> 5;
    const int lane = threadIdx.x & 31;
    const int row = blockIdx.x * 8 + wid;
    __shared__ float tv1[8][16], tv2[8][16];
    __shared__ int ti1[8][16], ti2[8][16];

    warp_top16(s1 + (size_t)row * NSUB, tv1[wid], ti1[wid], lane);
    warp_top16(s2 + (size_t)row * NSUB, tv2[wid], ti2[wid], lane);
    __syncwarp();

    float cv[8];
#pragma unroll
    for (int t = 0; t < 8; t++) {
        int c = lane * 8 + t;
        cv[t] = tv1[wid][c >> 4] + tv2[wid][c & 15];
    }
    float fv[8]; int fi[8];
#pragma unroll 1
    for (int it = 0; it < 8; it++) {
        float bv = cv[0]; int bt = 0;
#pragma unroll
        for (int t = 1; t < 8; t++) if (cv[t] > bv) { bv = cv[t]; bt = t; }
        int bidx = lane * 8 + bt;
#pragma unroll
        for (int off = 16; off; off >>= 1) {
            float ovv = __shfl_down_sync(0xffffffffu, bv, off);
            int oii = __shfl_down_sync(0xffffffffu, bidx, off);
            if (ovv > bv) { bv = ovv; bidx = oii; }
        }
        bv = __shfl_sync(0xffffffffu, bv, 0);
        bidx = __shfl_sync(0xffffffffu, bidx, 0);
        fv[it] = bv; fi[it] = bidx;
        if ((bidx >> 3) == lane) cv[bidx & 7] = NEG_INF;
    }

    if (lane < 8) {
        float m = fv[0];
        float sum = 0.f;
#pragma unroll
        for (int i = 0; i < 8; i++) sum += expf(fv[i] - m);
        float p = expf(fv[lane] - m) / sum;
        int c = fi[lane];
        int i1 = ti1[wid][c >> 4];
        int i2 = ti2[wid][c & 15];
        probs[(size_t)row * 8 + lane] = p;
        eidx[(size_t)row * 8 + lane] = i1 * NSUB + i2;
    }
}

// ---------------- MoE per-token: warp-per-expert, sync-free mainloop ----------------
__global__ void __launch_bounds__(256)
moe_kernel(const float* __restrict__ xproj, const float* __restrict__ Hall,
           const float* __restrict__ probs, const int* __restrict__ eidx,
           float* __restrict__ accb)
{
    const int n = blockIdx.x;
    const int t = threadIdx.x;
    const int lane = t & 31, w = t >> 5;
    __shared__ float part[8][DHIDDEN];

    float xpr[16];
#pragma unroll
    for (int j = 0; j < 16; j++)
        xpr[j] = xproj[(size_t)n * DHIDDEN + j * 32 + lane];

    float pa[16];
#pragma unroll
    for (int j = 0; j < 16; j++) pa[j] = 0.f;

#pragma unroll
    for (int je = 0; je < 4; je++) {
        const int s = w * 4 + je;
        const int e = eidx[n * 32 + s];
        const float* H = Hall + (size_t)e * DHIDDEN;
        float h[16];
#pragma unroll
        for (int j = 0; j < 16; j++) h[j] = H[j * 32 + lane];
        float dot = 0.f;
#pragma unroll
        for (int j = 0; j < 16; j++) dot = fmaf(xpr[j], h[j], dot);
#pragma unroll
        for (int off = 16; off; off >>= 1)
            dot += __shfl_xor_sync(0xffffffffu, dot, off);
        const float act = gelu_exact(dot) * probs[n * 32 + s];
#pragma unroll
        for (int j = 0; j < 16; j++) pa[j] = fmaf(act, h[j], pa[j]);
    }
#pragma unroll
    for (int j = 0; j < 16; j++) part[w][j * 32 + lane] = pa[j];
    __syncthreads();

    float a0 = 0.f, a1 = 0.f;
#pragma unroll
    for (int w2 = 0; w2 < 8; w2++) {
        a0 += part[w2][t];
        a1 += part[w2][t + 256];
    }
    accb[(size_t)n * DHIDDEN + t] = a0;
    accb[(size_t)n * DHIDDEN + 256 + t] = a1;
}

// ---------------- host launch ----------------
extern "C" void kernel_launch(void* const* d_in, const int* in_sizes, int n_in,
                              void* d_out, int out_size)
{
    const float* x       = (const float*)d_in[0];
    const float* Wq      = (const float*)d_in[1];
    const float* bq      = (const float*)d_in[2];
    const float* gamma   = (const float*)d_in[3];
    const float* beta    = (const float*)d_in[4];
    const float* sk1     = (const float*)d_in[5];
    const float* sk2     = (const float*)d_in[6];
    const float* latents = (const float*)d_in[7];
    const float* W1      = (const float*)d_in[8];
    const float* W2      = (const float*)d_in[9];
    float* out = (float*)d_out;

    void *pq, *ps1, *ps2, *psc, *psh, *pbp, *pH, *pxp, *pacc, *ppr, *pei, *pw1t, *pwvt;
    cudaGetSymbolAddress(&pq, g_q);
    cudaGetSymbolAddress(&ps1, g_s1);
    cudaGetSymbolAddress(&ps2, g_s2);
    cudaGetSymbolAddress(&psc, g_scale);
    cudaGetSymbolAddress(&psh, g_shift);
    cudaGetSymbolAddress(&pbp, g_bnpart);
    cudaGetSymbolAddress(&pH, g_Hall);
    cudaGetSymbolAddress(&pxp, g_xproj);
    cudaGetSymbolAddress(&pacc, g_acc);
    cudaGetSymbolAddress(&ppr, g_probs);
    cudaGetSymbolAddress(&pei, g_eidx);
    cudaGetSymbolAddress(&pw1t, g_W1T);
    cudaGetSymbolAddress(&pwvt, g_WvT);

    float* q_buf   = (float*)pq;
    float* s1_buf  = (float*)ps1;
    float* s2_buf  = (float*)ps2;
    float* sc_buf  = (float*)psc;
    float* sh_buf  = (float*)psh;
    float* bp_buf  = (float*)pbp;
    float* H_buf   = (float*)pH;
    float* xp_buf  = (float*)pxp;
    float* acc_buf = (float*)pacc;
    float* pr_buf  = (float*)ppr;
    int*   ei_buf  = (int*)pei;
    float* w1t_buf = (float*)pw1t;
    float* wvt_buf = (float*)pwvt;

    cudaFuncSetAttribute(mma_gemm<0>, cudaFuncAttributeMaxDynamicSharedMemorySize, GEMM_SMEM);
    cudaFuncSetAttribute(mma_gemm<1>, cudaFuncAttributeMaxDynamicSharedMemorySize, GEMM_SMEM);
    cudaFuncSetAttribute(tf32_gemm, cudaFuncAttributeMaxDynamicSharedMemorySize, TF_GEMM_SMEM);

    const dim3 blk(256);
    const dim3 tblk(32, 8);

    transpose_kernel<<<dim3(DHIDDEN / 32, DLATENT / 32), tblk>>>(W1, DHIDDEN, DLATENT, w1t_buf);
    transpose_kernel<<<dim3(DMODEL / 32, DHIDDEN / 32), tblk>>>(W2 + DMODEL, 2 * DMODEL, DHIDDEN, wvt_buf);

    // 1) q = x @ Wq^T + bq   (3xTF32)
    tf32_gemm<<<dim3(DMODEL / 128, N_TOK / 128), blk, TF_GEMM_SMEM>>>(
        x, DMODEL, Wq, DMODEL, q_buf, DMODEL, DMODEL, bq);

    // 2) batchnorm stats
    bn_part_kernel<<<dim3(DMODEL / 32, 8), blk>>>(q_buf, bp_buf);
    bn_final_kernel<<<DMODEL / 256, blk>>>(bp_buf, gamma, beta, sc_buf, sh_buf);

    // 6th launch: H_all GEMM (placed here so ncu -s 5 -c 1 captures it;
    // only depends on transpose of W1)
    mma_gemm<1><<<dim3(DHIDDEN / 128, NEXPERTS / 128), blk, GEMM_SMEM>>>(
        latents, DLATENT, w1t_buf, DLATENT, H_buf, DHIDDEN, DLATENT, nullptr, 1.0f);

    // 3) normalize
    normalize_kernel<<<(N_TOK * DMODEL / 4) / 256, blk>>>(q_buf, sc_buf, sh_buf);

    // 4) s1/s2 (3xTF32)
    tf32_gemm<<<dim3(1, (N_TOK * NHEADS) / 128), blk, TF_GEMM_SMEM>>>(
        q_buf, DQUERY, sk1, NSUB, s1_buf, NSUB, NSUB, nullptr);
    tf32_gemm<<<dim3(1, (N_TOK * NHEADS) / 128), blk, TF_GEMM_SMEM>>>(
        q_buf + 128, DQUERY, sk2, NSUB, s2_buf, NSUB, NSUB, nullptr);

    // 5) two-level top-k
    topk_kernel<<<(N_TOK * NHEADS) / 8, blk>>>(s1_buf, s2_buf, pr_buf, ei_buf);

    // 7) x_proj = x @ W2[:, :D]^T
    mma_gemm<0><<<dim3(DHIDDEN / 128, N_TOK / 128), blk, GEMM_SMEM>>>(
        x, DMODEL, W2, 2 * DMODEL, xp_buf, DHIDDEN, DMODEL, nullptr, 1.0f);

    // 8) MoE gather / act / accumulate
    moe_kernel<<<N_TOK, blk>>>(xp_buf, H_buf, pr_buf, ei_buf, acc_buf);

    // 9) out = acc @ WvT^T / 4
    mma_gemm<0><<<dim3(DMODEL / 128, N_TOK / 128), blk, GEMM_SMEM>>>(
        acc_buf, DHIDDEN, wvt_buf, DHIDDEN, out, DMODEL, DHIDDEN, nullptr, 0.25f);
}

// round 10
// speedup vs baseline: 1.2833x; 1.0731x over previous
#include <cuda_runtime.h>
#include <cuda_bf16.h>
#include <cuda_fp16.h>
#include <math.h>
#include <stdint.h>

#define N_TOK        8192
#define DMODEL       1024
#define DQUERY       256
#define NHEADS       4
#define NSUB         128
#define TOPK         8
#define DLATENT      256
#define DHIDDEN      512
#define NEXPERTS     16384
#define NEG_INF      (-1.0e38f)

// ---------------- scratch (device globals; no allocation allowed) ----------------
__device__ float g_q[N_TOK * DMODEL];
__device__ float g_s1[N_TOK * NHEADS * NSUB];
__device__ float g_s2[N_TOK * NHEADS * NSUB];
__device__ float g_scale[DMODEL];
__device__ float g_shift[DMODEL];
__device__ float g_bnpart[16 * DMODEL];
__device__ float g_Hall[NEXPERTS * DHIDDEN];
__device__ float g_xproj[N_TOK * DHIDDEN];
__device__ float g_acc[N_TOK * DHIDDEN];
__device__ float g_probs[N_TOK * NHEADS * TOPK];
__device__ int   g_eidx[N_TOK * NHEADS * TOPK];
__device__ float g_W1T[DHIDDEN * DLATENT];     // 512 x 256
__device__ float g_WvT[DMODEL * DHIDDEN];      // 1024 x 512

__device__ __forceinline__ float gelu_exact(float x) {
    return 0.5f * x * (1.0f + erff(x * 0.70710678118654752f));
}

__device__ __forceinline__ uint32_t smem_u32(const void* p) {
    uint32_t a;
    asm("{ .reg .u64 t; cvta.to.shared.u64 t, %1; cvt.u32.u64 %0, t; }" : "=r"(a) : "l"(p));
    return a;
}
__device__ __forceinline__ uint32_t sw128(uint32_t o) { return o ^ ((o >> 3) & 0x70); }

__device__ __forceinline__ void ldsm_x4(uint32_t* r, uint32_t addr) {
    asm volatile("ldmatrix.sync.aligned.m8n8.x4.shared.b16 {%0,%1,%2,%3}, [%4];"
                 : "=r"(r[0]), "=r"(r[1]), "=r"(r[2]), "=r"(r[3]) : "r"(addr));
}

// global chunk stage: 128 rows x 64 fp32 -> 8 float4 regs per thread
__device__ __forceinline__ void ch_ldg(const float* __restrict__ src, int ld,
                                       float4* r, int tid)
{
    const int r0 = tid >> 4;
    const int c  = (tid & 15) << 2;
#pragma unroll
    for (int p = 0; p < 8; p++)
        r[p] = *reinterpret_cast<const float4*>(src + (size_t)(r0 + (p << 4)) * ld + c);
}

#define TILE_BYTES 16384
#define STAGE_BYTES (4 * TILE_BYTES)
#define GEMM_SMEM  (2 * STAGE_BYTES + 1024)

// ================================================================
// fp16x4 HMMA GEMM (scoring path — near-fp32 accuracy, split err ~2^-33)
// C = A*B^T + bias ; A: MxK fp32 (lda), B: NxK fp32 (ldb); K%64==0
// ================================================================
__device__ __forceinline__ void mma16816h(float* d, const uint32_t* a, const uint32_t* b) {
    asm volatile(
        "mma.sync.aligned.m16n8k16.row.col.f32.f16.f16.f32 "
        "{%0,%1,%2,%3}, {%4,%5,%6,%7}, {%8,%9}, {%0,%1,%2,%3};"
        : "+f"(d[0]), "+f"(d[1]), "+f"(d[2]), "+f"(d[3])
        : "r"(a[0]), "r"(a[1]), "r"(a[2]), "r"(a[3]), "r"(b[0]), "r"(b[1]));
}

__device__ __forceinline__ void hp_cvt_sts(const float4* r,
                                           char* __restrict__ sm_hi,
                                           char* __restrict__ sm_lo, int tid)
{
    const int r0 = tid >> 4;
    const int c  = (tid & 15) << 2;
#pragma unroll
    for (int p = 0; p < 8; p++) {
        const int row = r0 + (p << 4);
        const float4 v = r[p];
        __half h0 = __float2half_rn(v.x);
        __half h1 = __float2half_rn(v.y);
        __half h2 = __float2half_rn(v.z);
        __half h3 = __float2half_rn(v.w);
        __half l0 = __float2half_rn(v.x - __half2float(h0));
        __half l1 = __float2half_rn(v.y - __half2float(h1));
        __half l2 = __float2half_rn(v.z - __half2float(h2));
        __half l3 = __float2half_rn(v.w - __half2float(h3));
        uint32_t hi01 = ((uint32_t)__half_as_ushort(h1) << 16) | __half_as_ushort(h0);
        uint32_t hi23 = ((uint32_t)__half_as_ushort(h3) << 16) | __half_as_ushort(h2);
        uint32_t lo01 = ((uint32_t)__half_as_ushort(l1) << 16) | __half_as_ushort(l0);
        uint32_t lo23 = ((uint32_t)__half_as_ushort(l3) << 16) | __half_as_ushort(l2);
        const uint32_t off = sw128((uint32_t)(row * 128 + (c << 1)));
        *reinterpret_cast<uint2*>(sm_hi + off) = make_uint2(hi01, hi23);
        *reinterpret_cast<uint2*>(sm_lo + off) = make_uint2(lo01, lo23);
    }
}

__global__ void __launch_bounds__(256, 1)
fp16_gemm(const float* __restrict__ A, int lda,
          const float* __restrict__ B, int ldb,
          float* __restrict__ C, int ldc, int K,
          const float* __restrict__ bias)
{
    extern __shared__ char dsm[];
    const uint32_t raw = smem_u32(dsm);
    const uint32_t base = (raw + 1023) & ~1023u;
    char* tiles = dsm + (base - raw);

    const int tid  = threadIdx.x;
    const int lane = tid & 31;
    const int wid  = tid >> 5;
    const int wm = wid & 3;
    const int wn = wid >> 2;
    const int bm = blockIdx.y * 128;
    const int bn = blockIdx.x * 128;

    const float* Ap = A + (size_t)bm * lda;
    const float* Bp = B + (size_t)bn * ldb;
    const int nk = K >> 6;

    float4 ra[8], rb[8];
    ch_ldg(Ap, lda, ra, tid);
    ch_ldg(Bp, ldb, rb, tid);
    hp_cvt_sts(ra, tiles, tiles + TILE_BYTES, tid);
    hp_cvt_sts(rb, tiles + 2 * TILE_BYTES, tiles + 3 * TILE_BYTES, tid);
    __syncthreads();

    float acc[2][8][4];
#pragma unroll
    for (int i = 0; i < 2; i++)
#pragma unroll
        for (int j = 0; j < 8; j++)
#pragma unroll
            for (int t = 0; t < 4; t++) acc[i][j][t] = 0.f;

    const int a_row = wm * 32 + (lane & 15);
    const int a_kb0 = (lane >> 4) << 4;
    const int b_row0 = wn * 64 + (lane & 7) + ((lane >> 4) << 3);
    const int b_kb0 = ((lane >> 3) & 1) << 4;

    for (int kc = 0; kc < nk; kc++) {
        const int cur = kc & 1;
        const bool more = (kc + 1 < nk);
        if (more) {
            ch_ldg(Ap + (kc + 1) * 64, lda, ra, tid);
            ch_ldg(Bp + (kc + 1) * 64, ldb, rb, tid);
        }
        const uint32_t sb = base + cur * STAGE_BYTES;
#pragma unroll
        for (int ks = 0; ks < 4; ks++) {
            uint32_t Ah[2][4], Al[2][4];
#pragma unroll
            for (int mf = 0; mf < 2; mf++) {
                uint32_t off = sw128((uint32_t)((a_row + mf * 16) * 128 + ks * 32 + a_kb0));
                ldsm_x4(Ah[mf], sb + off);
                ldsm_x4(Al[mf], sb + TILE_BYTES + off);
            }
            uint32_t Bh[4][4], Bl[4][4];
#pragma unroll
            for (int nf2 = 0; nf2 < 4; nf2++) {
                uint32_t off = sw128((uint32_t)((b_row0 + nf2 * 16) * 128 + ks * 32 + b_kb0));
                ldsm_x4(Bh[nf2], sb + 2 * TILE_BYTES + off);
                ldsm_x4(Bl[nf2], sb + 3 * TILE_BYTES + off);
            }
            // per-accumulator order: AhBh, AlBh, AhBl, AlBl
#pragma unroll
            for (int nf2 = 0; nf2 < 4; nf2++)
#pragma unroll
                for (int mf = 0; mf < 2; mf++) {
                    mma16816h(acc[mf][nf2 * 2 + 0], Ah[mf], Bh[nf2] + 0);
                    mma16816h(acc[mf][nf2 * 2 + 1], Ah[mf], Bh[nf2] + 2);
                }
#pragma unroll
            for (int nf2 = 0; nf2 < 4; nf2++)
#pragma unroll
                for (int mf = 0; mf < 2; mf++) {
                    mma16816h(acc[mf][nf2 * 2 + 0], Al[mf], Bh[nf2] + 0);
                    mma16816h(acc[mf][nf2 * 2 + 1], Al[mf], Bh[nf2] + 2);
                }
#pragma unroll
            for (int nf2 = 0; nf2 < 4; nf2++)
#pragma unroll
                for (int mf = 0; mf < 2; mf++) {
                    mma16816h(acc[mf][nf2 * 2 + 0], Ah[mf], Bl[nf2] + 0);
                    mma16816h(acc[mf][nf2 * 2 + 1], Ah[mf], Bl[nf2] + 2);
                }
#pragma unroll
            for (int nf2 = 0; nf2 < 4; nf2++)
#pragma unroll
                for (int mf = 0; mf < 2; mf++) {
                    mma16816h(acc[mf][nf2 * 2 + 0], Al[mf], Bl[nf2] + 0);
                    mma16816h(acc[mf][nf2 * 2 + 1], Al[mf], Bl[nf2] + 2);
                }
        }
        if (more) {
            char* st = tiles + (cur ^ 1) * STAGE_BYTES;
            hp_cvt_sts(ra, st, st + TILE_BYTES, tid);
            hp_cvt_sts(rb, st + 2 * TILE_BYTES, st + 3 * TILE_BYTES, tid);
        }
        __syncthreads();
    }

#pragma unroll
    for (int mf = 0; mf < 2; mf++) {
        const int row = bm + wm * 32 + mf * 16 + (lane >> 2);
#pragma unroll
        for (int nf = 0; nf < 8; nf++) {
            const int col = bn + wn * 64 + nf * 8 + (lane & 3) * 2;
            float b0 = 0.f, b1 = 0.f;
            if (bias) { b0 = bias[col]; b1 = bias[col + 1]; }
            *reinterpret_cast<float2*>(C + (size_t)row * ldc + col) =
                make_float2(acc[mf][nf][0] + b0, acc[mf][nf][1] + b1);
            *reinterpret_cast<float2*>(C + (size_t)(row + 8) * ldc + col) =
                make_float2(acc[mf][nf][2] + b0, acc[mf][nf][3] + b1);
        }
    }
}

// ================================================================
// bf16x3 HMMA GEMM (continuous GEMMs) — unchanged math
// ================================================================
__device__ __forceinline__ void mma16816(float* d, const uint32_t* a, const uint32_t* b) {
    asm volatile(
        "mma.sync.aligned.m16n8k16.row.col.f32.bf16.bf16.f32 "
        "{%0,%1,%2,%3}, {%4,%5,%6,%7}, {%8,%9}, {%0,%1,%2,%3};"
        : "+f"(d[0]), "+f"(d[1]), "+f"(d[2]), "+f"(d[3])
        : "r"(a[0]), "r"(a[1]), "r"(a[2]), "r"(a[3]), "r"(b[0]), "r"(b[1]));
}

__device__ __forceinline__ void bf_cvt_sts(const float4* r,
                                           char* __restrict__ sm_hi,
                                           char* __restrict__ sm_lo, int tid)
{
    const int r0 = tid >> 4;
    const int c  = (tid & 15) << 2;
#pragma unroll
    for (int p = 0; p < 8; p++) {
        const int row = r0 + (p << 4);
        const float4 v = r[p];
        __nv_bfloat16 h0 = __float2bfloat16(v.x);
        __nv_bfloat16 h1 = __float2bfloat16(v.y);
        __nv_bfloat16 h2 = __float2bfloat16(v.z);
        __nv_bfloat16 h3 = __float2bfloat16(v.w);
        __nv_bfloat16 l0 = __float2bfloat16(v.x - __bfloat162float(h0));
        __nv_bfloat16 l1 = __float2bfloat16(v.y - __bfloat162float(h1));
        __nv_bfloat16 l2 = __float2bfloat16(v.z - __bfloat162float(h2));
        __nv_bfloat16 l3 = __float2bfloat16(v.w - __bfloat162float(h3));
        uint32_t hi01 = ((uint32_t)__bfloat16_as_ushort(h1) << 16) | __bfloat16_as_ushort(h0);
        uint32_t hi23 = ((uint32_t)__bfloat16_as_ushort(h3) << 16) | __bfloat16_as_ushort(h2);
        uint32_t lo01 = ((uint32_t)__bfloat16_as_ushort(l1) << 16) | __bfloat16_as_ushort(l0);
        uint32_t lo23 = ((uint32_t)__bfloat16_as_ushort(l3) << 16) | __bfloat16_as_ushort(l2);
        const uint32_t off = sw128((uint32_t)(row * 128 + (c << 1)));
        *reinterpret_cast<uint2*>(sm_hi + off) = make_uint2(hi01, hi23);
        *reinterpret_cast<uint2*>(sm_lo + off) = make_uint2(lo01, lo23);
    }
}

template<int ACT>   // 0 = none, 1 = gelu
__global__ void __launch_bounds__(256, 1)
mma_gemm(const float* __restrict__ A, int lda,
         const float* __restrict__ B, int ldb,
         float* __restrict__ C, int ldc, int K,
         const float* __restrict__ bias, float scale)
{
    extern __shared__ char dsm[];
    const uint32_t raw = smem_u32(dsm);
    const uint32_t base = (raw + 1023) & ~1023u;
    char* tiles = dsm + (base - raw);

    const int tid  = threadIdx.x;
    const int lane = tid & 31;
    const int wid  = tid >> 5;
    const int wm = wid & 3;
    const int wn = wid >> 2;
    const int bm = blockIdx.y * 128;
    const int bn = blockIdx.x * 128;

    const float* Ap = A + (size_t)bm * lda;
    const float* Bp = B + (size_t)bn * ldb;
    const int nk = K >> 6;

    float4 ra[8], rb[8];
    ch_ldg(Ap, lda, ra, tid);
    ch_ldg(Bp, ldb, rb, tid);
    bf_cvt_sts(ra, tiles, tiles + TILE_BYTES, tid);
    bf_cvt_sts(rb, tiles + 2 * TILE_BYTES, tiles + 3 * TILE_BYTES, tid);
    __syncthreads();

    float acc[2][8][4];
#pragma unroll
    for (int i = 0; i < 2; i++)
#pragma unroll
        for (int j = 0; j < 8; j++)
#pragma unroll
            for (int t = 0; t < 4; t++) acc[i][j][t] = 0.f;

    const int a_row = wm * 32 + (lane & 15);
    const int a_kb0 = (lane >> 4) << 4;
    const int b_row0 = wn * 64 + (lane & 7) + ((lane >> 4) << 3);
    const int b_kb0 = ((lane >> 3) & 1) << 4;

    for (int kc = 0; kc < nk; kc++) {
        const int cur = kc & 1;
        const bool more = (kc + 1 < nk);
        if (more) {
            ch_ldg(Ap + (kc + 1) * 64, lda, ra, tid);
            ch_ldg(Bp + (kc + 1) * 64, ldb, rb, tid);
        }
        const uint32_t sb = base + cur * STAGE_BYTES;
#pragma unroll
        for (int ks = 0; ks < 4; ks++) {
            uint32_t Ah[2][4], Al[2][4];
#pragma unroll
            for (int mf = 0; mf < 2; mf++) {
                uint32_t off = sw128((uint32_t)((a_row + mf * 16) * 128 + ks * 32 + a_kb0));
                ldsm_x4(Ah[mf], sb + off);
                ldsm_x4(Al[mf], sb + TILE_BYTES + off);
            }
            uint32_t Bh[4][4], Bl[4][4];
#pragma unroll
            for (int nf2 = 0; nf2 < 4; nf2++) {
                uint32_t off = sw128((uint32_t)((b_row0 + nf2 * 16) * 128 + ks * 32 + b_kb0));
                ldsm_x4(Bh[nf2], sb + 2 * TILE_BYTES + off);
                ldsm_x4(Bl[nf2], sb + 3 * TILE_BYTES + off);
            }
            // per-accumulator order: AhBh, AlBh, AhBl
#pragma unroll
            for (int nf2 = 0; nf2 < 4; nf2++)
#pragma unroll
                for (int mf = 0; mf < 2; mf++) {
                    mma16816(acc[mf][nf2 * 2 + 0], Ah[mf], Bh[nf2] + 0);
                    mma16816(acc[mf][nf2 * 2 + 1], Ah[mf], Bh[nf2] + 2);
                }
#pragma unroll
            for (int nf2 = 0; nf2 < 4; nf2++)
#pragma unroll
                for (int mf = 0; mf < 2; mf++) {
                    mma16816(acc[mf][nf2 * 2 + 0], Al[mf], Bh[nf2] + 0);
                    mma16816(acc[mf][nf2 * 2 + 1], Al[mf], Bh[nf2] + 2);
                }
#pragma unroll
            for (int nf2 = 0; nf2 < 4; nf2++)
#pragma unroll
                for (int mf = 0; mf < 2; mf++) {
                    mma16816(acc[mf][nf2 * 2 + 0], Ah[mf], Bl[nf2] + 0);
                    mma16816(acc[mf][nf2 * 2 + 1], Ah[mf], Bl[nf2] + 2);
                }
        }
        if (more) {
            char* st = tiles + (cur ^ 1) * STAGE_BYTES;
            bf_cvt_sts(ra, st, st + TILE_BYTES, tid);
            bf_cvt_sts(rb, st + 2 * TILE_BYTES, st + 3 * TILE_BYTES, tid);
        }
        __syncthreads();
    }

#pragma unroll
    for (int mf = 0; mf < 2; mf++) {
        const int row = bm + wm * 32 + mf * 16 + (lane >> 2);
#pragma unroll
        for (int nf = 0; nf < 8; nf++) {
            const int col = bn + wn * 64 + nf * 8 + (lane & 3) * 2;
            float b0 = 0.f, b1 = 0.f;
            if (bias) { b0 = bias[col]; b1 = bias[col + 1]; }
            float v0 = acc[mf][nf][0] + b0;
            float v1 = acc[mf][nf][1] + b1;
            float v2 = acc[mf][nf][2] + b0;
            float v3 = acc[mf][nf][3] + b1;
            if (ACT == 1) {
                v0 = gelu_exact(v0); v1 = gelu_exact(v1);
                v2 = gelu_exact(v2); v3 = gelu_exact(v3);
            }
            v0 *= scale; v1 *= scale; v2 *= scale; v3 *= scale;
            *reinterpret_cast<float2*>(C + (size_t)row * ldc + col) = make_float2(v0, v1);
            *reinterpret_cast<float2*>(C + (size_t)(row + 8) * ldc + col) = make_float2(v2, v3);
        }
    }
}

// ---------------- transpose ----------------
__global__ void __launch_bounds__(256)
transpose_kernel(const float* __restrict__ src, int sld, int rows,
                 float* __restrict__ dst)
{
    __shared__ float t[32][33];
    const int bx = blockIdx.x * 32, by = blockIdx.y * 32;
    int x = bx + threadIdx.x, y = by + threadIdx.y;
#pragma unroll
    for (int i = 0; i < 32; i += 8)
        t[threadIdx.y + i][threadIdx.x] = src[(size_t)(y + i) * sld + x];
    __syncthreads();
    x = by + threadIdx.x; y = bx + threadIdx.y;
#pragma unroll
    for (int i = 0; i < 32; i += 8)
        dst[(size_t)(y + i) * rows + x] = t[threadIdx.x][threadIdx.y + i];
}

// ---------------- batchnorm: partial stats, then finalize ----------------
__global__ void __launch_bounds__(256)
bn_part_kernel(const float* __restrict__ q, float* __restrict__ part)
{
    const int lane32 = threadIdx.x & 31;
    const int grp = threadIdx.x >> 5;
    const int col = blockIdx.x * 32 + lane32;
    const int slice = blockIdx.y;
    const int r0 = slice * (N_TOK / 8);
    float s = 0.f, ss = 0.f;
    for (int r = grp; r < N_TOK / 8; r += 8) {
        float v = q[(size_t)(r0 + r) * DMODEL + col];
        s += v;
        ss += v * v;
    }
    __shared__ float sh_s[8][33], sh_q[8][33];
    sh_s[grp][lane32] = s;
    sh_q[grp][lane32] = ss;
    __syncthreads();
    if (grp == 0) {
        float ts = 0.f, tss = 0.f;
#pragma unroll
        for (int i = 0; i < 8; i++) { ts += sh_s[i][lane32]; tss += sh_q[i][lane32]; }
        part[(2 * slice + 0) * DMODEL + col] = ts;
        part[(2 * slice + 1) * DMODEL + col] = tss;
    }
}

__global__ void __launch_bounds__(256)
bn_final_kernel(const float* __restrict__ part,
                const float* __restrict__ gamma, const float* __restrict__ beta,
                float* __restrict__ scale, float* __restrict__ shift)
{
    const int col = blockIdx.x * 256 + threadIdx.x;
    float s = 0.f, ss = 0.f;
#pragma unroll
    for (int i = 0; i < 8; i++) {
        s  += part[(2 * i + 0) * DMODEL + col];
        ss += part[(2 * i + 1) * DMODEL + col];
    }
    float mean = s * (1.0f / N_TOK);
    float var = ss * (1.0f / N_TOK) - mean * mean;
    float rstd = rsqrtf(var + 1e-5f);
    float sc = gamma[col] * rstd;
    scale[col] = sc;
    shift[col] = beta[col] - mean * sc;
}

__global__ void __launch_bounds__(256)
normalize_kernel(float* __restrict__ q,
                 const float* __restrict__ scale, const float* __restrict__ shift)
{
    int i = blockIdx.x * blockDim.x + threadIdx.x;
    float4* q4 = reinterpret_cast<float4*>(q);
    float4 v = q4[i];
    int c = (i * 4) & (DMODEL - 1);
    v.x = v.x * scale[c + 0] + shift[c + 0];
    v.y = v.y * scale[c + 1] + shift[c + 1];
    v.z = v.z * scale[c + 2] + shift[c + 2];
    v.w = v.w * scale[c + 3] + shift[c + 3];
    q4[i] = v;
}

// ---------------- warp-collective top-16 of 128 values ----------------
__device__ __forceinline__ void warp_top16(const float* __restrict__ row,
                                           float* __restrict__ ov, int* __restrict__ oi,
                                           int lane)
{
    float v0 = row[lane], v1 = row[lane + 32], v2 = row[lane + 64], v3 = row[lane + 96];
#pragma unroll 1
    for (int it = 0; it < 16; it++) {
        float bv = v0; int bu = 0;
        if (v1 > bv) { bv = v1; bu = 1; }
        if (v2 > bv) { bv = v2; bu = 2; }
        if (v3 > bv) { bv = v3; bu = 3; }
        int bidx = lane + (bu << 5);
#pragma unroll
        for (int off = 16; off; off >>= 1) {
            float ovv = __shfl_down_sync(0xffffffffu, bv, off);
            int oii = __shfl_down_sync(0xffffffffu, bidx, off);
            if (ovv > bv) { bv = ovv; bidx = oii; }
        }
        bv = __shfl_sync(0xffffffffu, bv, 0);
        bidx = __shfl_sync(0xffffffffu, bidx, 0);
        if (lane == 0) { ov[it] = bv; oi[it] = bidx; }
        if ((bidx & 31) == lane) {
            int u = bidx >> 5;
            if (u == 0) v0 = NEG_INF;
            else if (u == 1) v1 = NEG_INF;
            else if (u == 2) v2 = NEG_INF;
            else v3 = NEG_INF;
        }
    }
}

__global__ void __launch_bounds__(256)
topk_kernel(const float* __restrict__ s1, const float* __restrict__ s2,
            float* __restrict__ probs, int* __restrict__ eidx)
{
    const int wid = threadIdx.x >> 5;
    const int lane = threadIdx.x & 31;
    const int row = blockIdx.x * 8 + wid;
    __shared__ float tv1[8][16], tv2[8][16];
    __shared__ int ti1[8][16], ti2[8][16];

    warp_top16(s1 + (size_t)row * NSUB, tv1[wid], ti1[wid], lane);
    warp_top16(s2 + (size_t)row * NSUB, tv2[wid], ti2[wid], lane);
    __syncwarp();

    float cv[8];
#pragma unroll
    for (int t = 0; t < 8; t++) {
        int c = lane * 8 + t;
        cv[t] = tv1[wid][c >> 4] + tv2[wid][c & 15];
    }
    float fv[8]; int fi[8];
#pragma unroll 1
    for (int it = 0; it < 8; it++) {
        float bv = cv[0]; int bt = 0;
#pragma unroll
        for (int t = 1; t < 8; t++) if (cv[t] > bv) { bv = cv[t]; bt = t; }
        int bidx = lane * 8 + bt;
#pragma unroll
        for (int off = 16; off; off >>= 1) {
            float ovv = __shfl_down_sync(0xffffffffu, bv, off);
            int oii = __shfl_down_sync(0xffffffffu, bidx, off);
            if (ovv > bv) { bv = ovv; bidx = oii; }
        }
        bv = __shfl_sync(0xffffffffu, bv, 0);
        bidx = __shfl_sync(0xffffffffu, bidx, 0);
        fv[it] = bv; fi[it] = bidx;
        if ((bidx >> 3) == lane) cv[bidx & 7] = NEG_INF;
    }

    if (lane < 8) {
        float m = fv[0];
        float sum = 0.f;
#pragma unroll
        for (int i = 0; i < 8; i++) sum += expf(fv[i] - m);
        float p = expf(fv[lane] - m) / sum;
        int c = fi[lane];
        int i1 = ti1[wid][c >> 4];
        int i2 = ti2[wid][c & 15];
        probs[(size_t)row * 8 + lane] = p;
        eidx[(size_t)row * 8 + lane] = i1 * NSUB + i2;
    }
}

// ---------------- MoE per-token: warp-per-expert, sync-free mainloop ----------------
__global__ void __launch_bounds__(256)
moe_kernel(const float* __restrict__ xproj, const float* __restrict__ Hall,
           const float* __restrict__ probs, const int* __restrict__ eidx,
           float* __restrict__ accb)
{
    const int n = blockIdx.x;
    const int t = threadIdx.x;
    const int lane = t & 31, w = t >> 5;
    __shared__ float part[8][DHIDDEN];

    float xpr[16];
#pragma unroll
    for (int j = 0; j < 16; j++)
        xpr[j] = xproj[(size_t)n * DHIDDEN + j * 32 + lane];

    float pa[16];
#pragma unroll
    for (int j = 0; j < 16; j++) pa[j] = 0.f;

#pragma unroll
    for (int je = 0; je < 4; je++) {
        const int s = w * 4 + je;
        const int e = eidx[n * 32 + s];
        const float* H = Hall + (size_t)e * DHIDDEN;
        float h[16];
#pragma unroll
        for (int j = 0; j < 16; j++) h[j] = H[j * 32 + lane];
        float dot = 0.f;
#pragma unroll
        for (int j = 0; j < 16; j++) dot = fmaf(xpr[j], h[j], dot);
#pragma unroll
        for (int off = 16; off; off >>= 1)
            dot += __shfl_xor_sync(0xffffffffu, dot, off);
        const float act = gelu_exact(dot) * probs[n * 32 + s];
#pragma unroll
        for (int j = 0; j < 16; j++) pa[j] = fmaf(act, h[j], pa[j]);
    }
#pragma unroll
    for (int j = 0; j < 16; j++) part[w][j * 32 + lane] = pa[j];
    __syncthreads();

    float a0 = 0.f, a1 = 0.f;
#pragma unroll
    for (int w2 = 0; w2 < 8; w2++) {
        a0 += part[w2][t];
        a1 += part[w2][t + 256];
    }
    accb[(size_t)n * DHIDDEN + t] = a0;
    accb[(size_t)n * DHIDDEN + 256 + t] = a1;
}

// ---------------- host launch ----------------
extern "C" void kernel_launch(void* const* d_in, const int* in_sizes, int n_in,
                              void* d_out, int out_size)
{
    const float* x       = (const float*)d_in[0];
    const float* Wq      = (const float*)d_in[1];
    const float* bq      = (const float*)d_in[2];
    const float* gamma   = (const float*)d_in[3];
    const float* beta    = (const float*)d_in[4];
    const float* sk1     = (const float*)d_in[5];
    const float* sk2     = (const float*)d_in[6];
    const float* latents = (const float*)d_in[7];
    const float* W1      = (const float*)d_in[8];
    const float* W2      = (const float*)d_in[9];
    float* out = (float*)d_out;

    void *pq, *ps1, *ps2, *psc, *psh, *pbp, *pH, *pxp, *pacc, *ppr, *pei, *pw1t, *pwvt;
    cudaGetSymbolAddress(&pq, g_q);
    cudaGetSymbolAddress(&ps1, g_s1);
    cudaGetSymbolAddress(&ps2, g_s2);
    cudaGetSymbolAddress(&psc, g_scale);
    cudaGetSymbolAddress(&psh, g_shift);
    cudaGetSymbolAddress(&pbp, g_bnpart);
    cudaGetSymbolAddress(&pH, g_Hall);
    cudaGetSymbolAddress(&pxp, g_xproj);
    cudaGetSymbolAddress(&pacc, g_acc);
    cudaGetSymbolAddress(&ppr, g_probs);
    cudaGetSymbolAddress(&pei, g_eidx);
    cudaGetSymbolAddress(&pw1t, g_W1T);
    cudaGetSymbolAddress(&pwvt, g_WvT);

    float* q_buf   = (float*)pq;
    float* s1_buf  = (float*)ps1;
    float* s2_buf  = (float*)ps2;
    float* sc_buf  = (float*)psc;
    float* sh_buf  = (float*)psh;
    float* bp_buf  = (float*)pbp;
    float* H_buf   = (float*)pH;
    float* xp_buf  = (float*)pxp;
    float* acc_buf = (float*)pacc;
    float* pr_buf  = (float*)ppr;
    int*   ei_buf  = (int*)pei;
    float* w1t_buf = (float*)pw1t;
    float* wvt_buf = (float*)pwvt;

    cudaFuncSetAttribute(mma_gemm<0>, cudaFuncAttributeMaxDynamicSharedMemorySize, GEMM_SMEM);
    cudaFuncSetAttribute(mma_gemm<1>, cudaFuncAttributeMaxDynamicSharedMemorySize, GEMM_SMEM);
    cudaFuncSetAttribute(fp16_gemm, cudaFuncAttributeMaxDynamicSharedMemorySize, GEMM_SMEM);

    const dim3 blk(256);
    const dim3 tblk(32, 8);

    transpose_kernel<<<dim3(DHIDDEN / 32, DLATENT / 32), tblk>>>(W1, DHIDDEN, DLATENT, w1t_buf);
    transpose_kernel<<<dim3(DMODEL / 32, DHIDDEN / 32), tblk>>>(W2 + DMODEL, 2 * DMODEL, DHIDDEN, wvt_buf);

    // 1) q = x @ Wq^T + bq   (fp16x4 — near-fp32 accuracy)
    fp16_gemm<<<dim3(DMODEL / 128, N_TOK / 128), blk, GEMM_SMEM>>>(
        x, DMODEL, Wq, DMODEL, q_buf, DMODEL, DMODEL, bq);

    // 2) batchnorm stats
    bn_part_kernel<<<dim3(DMODEL / 32, 8), blk>>>(q_buf, bp_buf);
    bn_final_kernel<<<DMODEL / 256, blk>>>(bp_buf, gamma, beta, sc_buf, sh_buf);

    // H_all GEMM (independent of scoring chain; placed early)
    mma_gemm<1><<<dim3(DHIDDEN / 128, NEXPERTS / 128), blk, GEMM_SMEM>>>(
        latents, DLATENT, w1t_buf, DLATENT, H_buf, DHIDDEN, DLATENT, nullptr, 1.0f);

    // 3) normalize
    normalize_kernel<<<(N_TOK * DMODEL / 4) / 256, blk>>>(q_buf, sc_buf, sh_buf);

    // 4) s1/s2 (fp16x4)
    fp16_gemm<<<dim3(1, (N_TOK * NHEADS) / 128), blk, GEMM_SMEM>>>(
        q_buf, DQUERY, sk1, NSUB, s1_buf, NSUB, NSUB, nullptr);
    fp16_gemm<<<dim3(1, (N_TOK * NHEADS) / 128), blk, GEMM_SMEM>>>(
        q_buf + 128, DQUERY, sk2, NSUB, s2_buf, NSUB, NSUB, nullptr);

    // 5) two-level top-k
    topk_kernel<<<(N_TOK * NHEADS) / 8, blk>>>(s1_buf, s2_buf, pr_buf, ei_buf);

    // 7) x_proj = x @ W2[:, :D]^T
    mma_gemm<0><<<dim3(DHIDDEN / 128, N_TOK / 128), blk, GEMM_SMEM>>>(
        x, DMODEL, W2, 2 * DMODEL, xp_buf, DHIDDEN, DMODEL, nullptr, 1.0f);

    // 8) MoE gather / act / accumulate
    moe_kernel<<<N_TOK, blk>>>(xp_buf, H_buf, pr_buf, ei_buf, acc_buf);

    // 9) out = acc @ WvT^T / 4
    mma_gemm<0><<<dim3(DMODEL / 128, N_TOK / 128), blk, GEMM_SMEM>>>(
        acc_buf, DHIDDEN, wvt_buf, DHIDDEN, out, DMODEL, DHIDDEN, nullptr, 0.25f);
}